// round 1
// baseline (speedup 1.0000x reference)
#include <cuda_runtime.h>
#include <cstdint>

// Problem constants
#define B_    32
#define CIN_  12
#define LEN_  1024
#define TT_   64
#define C1_   64
#define C2_   128

// Scratch (device globals; no runtime allocation)
__device__ float         g_xT[TT_ * B_ * CIN_ * LEN_];            // 96 MB   [t][b][cin][l]
__device__ unsigned char g_s1[TT_ * B_ * C1_ * LEN_];             // 128 MB  [t][b][c1][l]
__device__ float         g_h2[(size_t)TT_ * B_ * C2_ * LEN_];     // 1 GB    [t][b][c2][l]
__device__ float         g_pool[B_ * C2_];

typedef unsigned long long u64;

// ---- packed f32x2 helpers (Blackwell FFMA2 path; ptxas never auto-fuses) ----
__device__ __forceinline__ u64 pack2(float lo, float hi) {
    u64 r;
    asm("mov.b64 %0, {%1, %2};" : "=l"(r) : "f"(lo), "f"(hi));
    return r;
}
__device__ __forceinline__ void unpack2(u64 v, float& lo, float& hi) {
    asm("mov.b64 {%0, %1}, %2;" : "=f"(lo), "=f"(hi) : "l"(v));
}
__device__ __forceinline__ void ffma2(u64& d, u64 a, u64 b) {
    asm("fma.rn.f32x2 %0, %1, %2, %0;" : "+l"(d) : "l"(a), "l"(b));
}

// ============================================================================
// Kernel 0: transpose x [b][cin][l][t] -> g_xT [t][b][cin][l]
// ============================================================================
__global__ void __launch_bounds__(256) transpose_kernel(const float* __restrict__ x) {
    __shared__ float tile[32][33];
    const int bc = blockIdx.z;          // b*12 + cin
    const int t0 = blockIdx.x * 32;
    const int l0 = blockIdx.y * 32;
    const int tx = threadIdx.x;         // 32
    const int ty = threadIdx.y;         // 8
    const float* xb = x + (size_t)bc * LEN_ * TT_;
#pragma unroll
    for (int j = 0; j < 4; ++j)
        tile[ty + j * 8][tx] = xb[(size_t)(l0 + ty + j * 8) * TT_ + t0 + tx];
    __syncthreads();
#pragma unroll
    for (int j = 0; j < 4; ++j)
        g_xT[((size_t)(t0 + ty + j * 8) * (B_ * CIN_) + bc) * LEN_ + l0 + tx] =
            tile[tx][ty + j * 8];
}

// ============================================================================
// Kernel 1: conv1 (12->64, K=7, same pad) + LIF1 (tau=1 -> stateless spike)
// grid (L/128, B, T), block 256. Thread: 8 c1 x 4 l. f32x2 FMAs.
// ============================================================================
__global__ void __launch_bounds__(256) conv1_kernel(const float* __restrict__ w1,
                                                    const float* __restrict__ b1) {
    __shared__ float ws[84 * 68];       // [(cin*7+k)*68 + c1], pitch 68 (16B-aligned, low conflicts)
    __shared__ float xs[12][136];       // covers l0-3 .. l0+130

    const int tid = threadIdx.x;
    const int l0  = blockIdx.x * 128;
    const int b   = blockIdx.y;
    const int t   = blockIdx.z;

    for (int i = tid; i < C1_ * 84; i += 256) {
        int c1 = i / 84, r = i % 84;    // r = cin*7 + k
        ws[r * 68 + c1] = w1[i];
    }
    const float* xb = g_xT + ((size_t)(t * B_ + b) * CIN_) * LEN_;
    for (int i = tid; i < 12 * 134; i += 256) {
        int cin = i / 134, j = i % 134;
        int l = l0 - 3 + j;
        xs[cin][j] = (l >= 0 && l < LEN_) ? xb[cin * LEN_ + l] : 0.f;
    }
    __syncthreads();

    const int c1g = tid >> 5;           // 0..7 -> c1 = c1g*8 .. +7
    const int lg  = tid & 31;           // l = l0 + lg*4 .. +3

    u64 acc[8][2];
#pragma unroll
    for (int c = 0; c < 8; ++c) { acc[c][0] = 0ull; acc[c][1] = 0ull; }

#pragma unroll 1
    for (int cin = 0; cin < 12; ++cin) {
        const float* sp = &xs[cin][lg * 4];
        float4 a0 = *reinterpret_cast<const float4*>(sp);
        float4 a1 = *reinterpret_cast<const float4*>(sp + 4);
        float4 a2 = *reinterpret_cast<const float4*>(sp + 8);
        float sv[12] = {a0.x, a0.y, a0.z, a0.w, a1.x, a1.y, a1.z, a1.w,
                        a2.x, a2.y, a2.z, a2.w};
        u64 pv[9];
#pragma unroll
        for (int j = 0; j < 9; ++j) pv[j] = pack2(sv[j], sv[j + 1]);
#pragma unroll
        for (int k = 0; k < 7; ++k) {
            const float* wp = &ws[(cin * 7 + k) * 68 + c1g * 8];
            float4 w0 = *reinterpret_cast<const float4*>(wp);
            float4 w1v = *reinterpret_cast<const float4*>(wp + 4);
            float wr[8] = {w0.x, w0.y, w0.z, w0.w, w1v.x, w1v.y, w1v.z, w1v.w};
#pragma unroll
            for (int c = 0; c < 8; ++c) {
                u64 wb = pack2(wr[c], wr[c]);
                ffma2(acc[c][0], pv[k], wb);
                ffma2(acc[c][1], pv[k + 2], wb);
            }
        }
    }

    unsigned char* sb = g_s1 + ((size_t)(t * B_ + b) * C1_) * LEN_;
#pragma unroll
    for (int c = 0; c < 8; ++c) {
        int c1 = c1g * 8 + c;
        float bb = b1[c1];
        float v0, v1, v2, v3;
        unpack2(acc[c][0], v0, v1);
        unpack2(acc[c][1], v2, v3);
        uchar4 o;
        o.x = (2.f * (v0 + bb) >= 0.5f) ? 1 : 0;
        o.y = (2.f * (v1 + bb) >= 0.5f) ? 1 : 0;
        o.z = (2.f * (v2 + bb) >= 0.5f) ? 1 : 0;
        o.w = (2.f * (v3 + bb) >= 0.5f) ? 1 : 0;
        *reinterpret_cast<uchar4*>(sb + (size_t)c1 * LEN_ + l0 + lg * 4) = o;
    }
}

// ============================================================================
// Kernel 2: conv2 (64->128, K=7) on spikes, all T in parallel -> h2
// grid (L/128, B, T), block 256. Thread: 8 c2 x 8 l. c1 chunked (4 x 16).
// Dynamic smem: s1 tile [64][136] + w2 chunk [112][132]
// ============================================================================
extern __shared__ float c2smem[];
__global__ void __launch_bounds__(256) conv2_kernel(const float* __restrict__ w2,
                                                    const float* __restrict__ b2) {
    float (*s1s)[136] = reinterpret_cast<float(*)[136]>(c2smem);
    float* w2s = c2smem + 64 * 136;     // [r][c2] pitch 132, r = cc*7+k

    const int tid = threadIdx.x;
    const int l0  = blockIdx.x * 128;
    const int b   = blockIdx.y;
    const int t   = blockIdx.z;

    const unsigned char* sb = g_s1 + ((size_t)(t * B_ + b) * C1_) * LEN_;
    for (int i = tid; i < 64 * 134; i += 256) {
        int c1 = i / 134, j = i % 134;
        int l = l0 - 3 + j;
        s1s[c1][j] = (l >= 0 && l < LEN_) ? (float)sb[c1 * LEN_ + l] : 0.f;
    }

    const int c2g = tid >> 4;           // 0..15 -> c2 = c2g*8 .. +7
    const int lg  = tid & 15;           // l = l0 + lg*8 .. +7

    u64 acc[8][4];
#pragma unroll
    for (int c = 0; c < 8; ++c)
#pragma unroll
        for (int p = 0; p < 4; ++p) acc[c][p] = 0ull;

#pragma unroll 1
    for (int ch = 0; ch < 4; ++ch) {
        __syncthreads();
        // stage w2 chunk: c1 in [ch*16, ch*16+16); global reads coalesced (112-float runs)
        for (int i = tid; i < 128 * 112; i += 256) {
            int c2 = i / 112, r = i % 112;
            w2s[r * 132 + c2] = w2[c2 * 448 + ch * 112 + r];
        }
        __syncthreads();

#pragma unroll 1
        for (int cc = 0; cc < 16; ++cc) {
            const float* sp = &s1s[ch * 16 + cc][lg * 8];
            float4 q0 = *reinterpret_cast<const float4*>(sp);
            float4 q1 = *reinterpret_cast<const float4*>(sp + 4);
            float4 q2 = *reinterpret_cast<const float4*>(sp + 8);
            float4 q3 = *reinterpret_cast<const float4*>(sp + 12);
            float sv[16] = {q0.x, q0.y, q0.z, q0.w, q1.x, q1.y, q1.z, q1.w,
                            q2.x, q2.y, q2.z, q2.w, q3.x, q3.y, q3.z, q3.w};
            u64 pv[13];
#pragma unroll
            for (int j = 0; j < 13; ++j) pv[j] = pack2(sv[j], sv[j + 1]);
#pragma unroll
            for (int k = 0; k < 7; ++k) {
                const float* wp = &w2s[(cc * 7 + k) * 132 + c2g * 8];
                float4 w0 = *reinterpret_cast<const float4*>(wp);
                float4 w1v = *reinterpret_cast<const float4*>(wp + 4);
                float wr[8] = {w0.x, w0.y, w0.z, w0.w, w1v.x, w1v.y, w1v.z, w1v.w};
#pragma unroll
                for (int c = 0; c < 8; ++c) {
                    u64 wb = pack2(wr[c], wr[c]);
#pragma unroll
                    for (int lp = 0; lp < 4; ++lp)
                        ffma2(acc[c][lp], pv[k + 2 * lp], wb);
                }
            }
        }
    }

    float* hb = g_h2 + ((size_t)(t * B_ + b) * C2_) * LEN_ + l0 + lg * 8;
#pragma unroll
    for (int c = 0; c < 8; ++c) {
        int c2 = c2g * 8 + c;
        float bb = b2[c2];
        float v0, v1, v2, v3, v4, v5, v6, v7;
        unpack2(acc[c][0], v0, v1);
        unpack2(acc[c][1], v2, v3);
        unpack2(acc[c][2], v4, v5);
        unpack2(acc[c][3], v6, v7);
        float4 o0 = make_float4(2.f * (v0 + bb), 2.f * (v1 + bb),
                                2.f * (v2 + bb), 2.f * (v3 + bb));
        float4 o1 = make_float4(2.f * (v4 + bb), 2.f * (v5 + bb),
                                2.f * (v6 + bb), 2.f * (v7 + bb));
        *reinterpret_cast<float4*>(hb + (size_t)c2 * LEN_)     = o0;
        *reinterpret_cast<float4*>(hb + (size_t)c2 * LEN_ + 4) = o1;
    }
}

// ============================================================================
// Kernel 3: LIF2 scan over T + spike accumulation + mean over L -> g_pool
// grid (B*C2), block 256, 4 l per thread (float4)
// ============================================================================
__global__ void __launch_bounds__(256) lif2_kernel() {
    __shared__ float red[256];
    const int bc  = blockIdx.x;         // b*128 + c2
    const int tid = threadIdx.x;
    const float* base = g_h2 + (size_t)bc * LEN_ + tid * 4;

    float4 v = make_float4(0.f, 0.f, 0.f, 0.f);
    float4 a = make_float4(0.f, 0.f, 0.f, 0.f);
#pragma unroll 4
    for (int t = 0; t < TT_; ++t) {
        float4 h = *reinterpret_cast<const float4*>(base + (size_t)t * B_ * C2_ * LEN_);
        v.x += __fdiv_rn(h.x - v.x, 0.9f); if (v.x >= 0.5f) { a.x += 1.f; v.x = 0.f; }
        v.y += __fdiv_rn(h.y - v.y, 0.9f); if (v.y >= 0.5f) { a.y += 1.f; v.y = 0.f; }
        v.z += __fdiv_rn(h.z - v.z, 0.9f); if (v.z >= 0.5f) { a.z += 1.f; v.z = 0.f; }
        v.w += __fdiv_rn(h.w - v.w, 0.9f); if (v.w >= 0.5f) { a.w += 1.f; v.w = 0.f; }
    }
    red[tid] = a.x + a.y + a.z + a.w;
    __syncthreads();
    for (int s = 128; s > 0; s >>= 1) {
        if (tid < s) red[tid] += red[tid + s];
        __syncthreads();
    }
    if (tid == 0) g_pool[bc] = red[0] * (1.f / (float)(TT_ * LEN_));
}

// ============================================================================
// Kernel 4: FC [32,128] x [4,128]^T + bias -> out [32,4]
// ============================================================================
__global__ void fc_kernel(const float* __restrict__ fcw,
                          const float* __restrict__ fcb,
                          float* __restrict__ out) {
    const int tid = threadIdx.x;
    if (tid < B_ * 4) {
        int b = tid >> 2, n = tid & 3;
        float s = 0.f;
#pragma unroll 8
        for (int c = 0; c < C2_; ++c)
            s += g_pool[b * C2_ + c] * fcw[n * C2_ + c];
        out[b * 4 + n] = s + fcb[n];
    }
}

// ============================================================================
extern "C" void kernel_launch(void* const* d_in, const int* in_sizes, int n_in,
                              void* d_out, int out_size) {
    const float* x   = (const float*)d_in[0];
    const float* w1  = (const float*)d_in[1];
    const float* b1  = (const float*)d_in[2];
    const float* w2  = (const float*)d_in[3];
    const float* b2  = (const float*)d_in[4];
    const float* fcw = (const float*)d_in[5];
    const float* fcb = (const float*)d_in[6];
    float* out = (float*)d_out;

    const int conv2_smem = (64 * 136 + 112 * 132) * (int)sizeof(float);  // 93952 B
    cudaFuncSetAttribute(conv2_kernel, cudaFuncAttributeMaxDynamicSharedMemorySize,
                         conv2_smem);

    transpose_kernel<<<dim3(TT_ / 32, LEN_ / 32, B_ * CIN_), dim3(32, 8)>>>(x);
    conv1_kernel<<<dim3(LEN_ / 128, B_, TT_), 256>>>(w1, b1);
    conv2_kernel<<<dim3(LEN_ / 128, B_, TT_), 256, conv2_smem>>>(w2, b2);
    lif2_kernel<<<B_ * C2_, 256>>>();
    fc_kernel<<<1, 128>>>(fcw, fcb, out);
}

// round 3
// speedup vs baseline: 1.1101x; 1.1101x over previous
#include <cuda_runtime.h>
#include <cuda_bf16.h>
#include <cstdint>

#define B_    32
#define CIN_  12
#define LEN_  1024
#define TT_   64
#define C1_   64
#define C2_   128

// Scratch (device globals; no runtime allocation)
__device__ float         g_xT[TT_ * B_ * CIN_ * LEN_];   // [t][b][cin][l]
__device__ unsigned char g_s1[TT_ * B_ * C1_ * LEN_];    // [t][b][c1][l]
__device__ uint4         g_Apk[14336];                   // packed w2 fragments (2 c2h x 2 planes x 4 mt x 28 ch x 32 lanes)
__device__ float         g_pool[B_ * C2_];               // spike sums per (b, c2)

typedef unsigned long long u64;

// ---- packed f32x2 helpers (conv1 FFMA2 path) ----
__device__ __forceinline__ u64 pack2(float lo, float hi) {
    u64 r;
    asm("mov.b64 %0, {%1, %2};" : "=l"(r) : "f"(lo), "f"(hi));
    return r;
}
__device__ __forceinline__ void unpack2(u64 v, float& lo, float& hi) {
    asm("mov.b64 {%0, %1}, %2;" : "=f"(lo), "=f"(hi) : "l"(v));
}
__device__ __forceinline__ void ffma2(u64& d, u64 a, u64 b) {
    asm("fma.rn.f32x2 %0, %1, %2, %0;" : "+l"(d) : "l"(a), "l"(b));
}

// ---- warp MMA: m16n8k16 bf16 -> f32 (baseline PTX, works at .target sm_103) ----
#define MMA16816(D, A, B0, B1)                                               \
    asm volatile(                                                            \
        "mma.sync.aligned.m16n8k16.row.col.f32.bf16.bf16.f32 "               \
        "{%0,%1,%2,%3}, {%4,%5,%6,%7}, {%8,%9}, {%0,%1,%2,%3};"              \
        : "+f"((D)[0]), "+f"((D)[1]), "+f"((D)[2]), "+f"((D)[3])             \
        : "r"((A).x), "r"((A).y), "r"((A).z), "r"((A).w), "r"(B0), "r"(B1))

// ============================================================================
// Kernel 0: transpose x [b][cin][l][t] -> g_xT [t][b][cin][l]
// ============================================================================
__global__ void __launch_bounds__(256) transpose_kernel(const float* __restrict__ x) {
    __shared__ float tile[32][33];
    const int bc = blockIdx.z;
    const int t0 = blockIdx.x * 32;
    const int l0 = blockIdx.y * 32;
    const int tx = threadIdx.x;
    const int ty = threadIdx.y;
    const float* xb = x + (size_t)bc * LEN_ * TT_;
#pragma unroll
    for (int j = 0; j < 4; ++j)
        tile[ty + j * 8][tx] = xb[(size_t)(l0 + ty + j * 8) * TT_ + t0 + tx];
    __syncthreads();
#pragma unroll
    for (int j = 0; j < 4; ++j)
        g_xT[((size_t)(t0 + ty + j * 8) * (B_ * CIN_) + bc) * LEN_ + l0 + tx] =
            tile[tx][ty + j * 8];
}

// ============================================================================
// Kernel 1: conv1 (12->64, K=7) + LIF1 (tau=1 -> stateless spike), FFMA2
// ============================================================================
__global__ void __launch_bounds__(256) conv1_kernel(const float* __restrict__ w1,
                                                    const float* __restrict__ b1) {
    __shared__ float ws[84 * 68];
    __shared__ float xs[12][136];

    const int tid = threadIdx.x;
    const int l0  = blockIdx.x * 128;
    const int b   = blockIdx.y;
    const int t   = blockIdx.z;

    for (int i = tid; i < C1_ * 84; i += 256) {
        int c1 = i / 84, r = i % 84;
        ws[r * 68 + c1] = w1[i];
    }
    const float* xb = g_xT + ((size_t)(t * B_ + b) * CIN_) * LEN_;
    for (int i = tid; i < 12 * 134; i += 256) {
        int cin = i / 134, j = i % 134;
        int l = l0 - 3 + j;
        xs[cin][j] = (l >= 0 && l < LEN_) ? xb[cin * LEN_ + l] : 0.f;
    }
    __syncthreads();

    const int c1g = tid >> 5;
    const int lg  = tid & 31;

    u64 acc[8][2];
#pragma unroll
    for (int c = 0; c < 8; ++c) { acc[c][0] = 0ull; acc[c][1] = 0ull; }

#pragma unroll 1
    for (int cin = 0; cin < 12; ++cin) {
        const float* sp = &xs[cin][lg * 4];
        float4 a0 = *reinterpret_cast<const float4*>(sp);
        float4 a1 = *reinterpret_cast<const float4*>(sp + 4);
        float4 a2 = *reinterpret_cast<const float4*>(sp + 8);
        float sv[12] = {a0.x, a0.y, a0.z, a0.w, a1.x, a1.y, a1.z, a1.w,
                        a2.x, a2.y, a2.z, a2.w};
        u64 pv[9];
#pragma unroll
        for (int j = 0; j < 9; ++j) pv[j] = pack2(sv[j], sv[j + 1]);
#pragma unroll
        for (int k = 0; k < 7; ++k) {
            const float* wp = &ws[(cin * 7 + k) * 68 + c1g * 8];
            float4 w0 = *reinterpret_cast<const float4*>(wp);
            float4 w1v = *reinterpret_cast<const float4*>(wp + 4);
            float wr[8] = {w0.x, w0.y, w0.z, w0.w, w1v.x, w1v.y, w1v.z, w1v.w};
#pragma unroll
            for (int c = 0; c < 8; ++c) {
                u64 wb = pack2(wr[c], wr[c]);
                ffma2(acc[c][0], pv[k], wb);
                ffma2(acc[c][1], pv[k + 2], wb);
            }
        }
    }

    unsigned char* sb = g_s1 + ((size_t)(t * B_ + b) * C1_) * LEN_;
#pragma unroll
    for (int c = 0; c < 8; ++c) {
        int c1 = c1g * 8 + c;
        float bb = b1[c1];
        float v0, v1, v2, v3;
        unpack2(acc[c][0], v0, v1);
        unpack2(acc[c][1], v2, v3);
        uchar4 o;
        o.x = (2.f * (v0 + bb) >= 0.5f) ? 1 : 0;
        o.y = (2.f * (v1 + bb) >= 0.5f) ? 1 : 0;
        o.z = (2.f * (v2 + bb) >= 0.5f) ? 1 : 0;
        o.w = (2.f * (v3 + bb) >= 0.5f) ? 1 : 0;
        *reinterpret_cast<uchar4*>(sb + (size_t)c1 * LEN_ + l0 + lg * 4) = o;
    }
}

// ============================================================================
// Kernel 2a: pack w2 into mma-fragment order, split bf16 hi/lo planes.
// K order: chunk = koff*4 + q  ->  c1 = q*16 + kk  (B side uses same order)
// ============================================================================
__global__ void __launch_bounds__(256) w2prep_kernel(const float* __restrict__ w2) {
    int idx = blockIdx.x * 256 + threadIdx.x;
    if (idx >= 14336) return;
    int lane  = idx & 31;
    int rest  = idx >> 5;
    int chunk = rest % 28;
    int rest2 = rest / 28;
    int mt    = rest2 & 3;
    int plane = (rest2 >> 2) & 1;
    int c2h   = rest2 >> 3;
    int g = lane >> 2, c = lane & 3;
    int q = chunk & 3, koff = chunk >> 2;
    int m0 = c2h * 64 + mt * 16;

    auto cv = [&](int m, int c1) -> unsigned {
        float w = w2[m * 448 + c1 * 7 + koff];
        __nv_bfloat16 h = __float2bfloat16(w);
        if (plane) h = __float2bfloat16(w - __bfloat162float(h));
        return (unsigned)__bfloat16_as_ushort(h);
    };
    int c1a = q * 16 + 2 * c;
    int c1b = c1a + 8;
    uint4 r;
    r.x = cv(m0 + g,     c1a) | (cv(m0 + g,     c1a + 1) << 16);
    r.y = cv(m0 + g + 8, c1a) | (cv(m0 + g + 8, c1a + 1) << 16);
    r.z = cv(m0 + g,     c1b) | (cv(m0 + g,     c1b + 1) << 16);
    r.w = cv(m0 + g + 8, c1b) | (cv(m0 + g + 8, c1b + 1) << 16);
    g_Apk[idx] = r;
}

// ============================================================================
// Kernel 2b: conv2 via mma.sync + fused LIF2.
// Block: 64 c2 (c2h half) x 128 l; 8 warps (2 x 4): warp tile M=32, N=32.
// A (packed frags, both planes) staged to smem once; spikes re-transposed
// per t into double-buffered spT[134][72] bf16 (pitch 144B, conflict-free).
// LIF state lives in registers across the t-loop. Spike counts (integers)
// pooled via exact atomicAdd.
// ============================================================================
#define APK_U4    7168          // uint4 per c2h
#define SPT_PITCH 144
#define SPT_ROWS  134
#define SPT_OFF0  114688
#define SPT_OFF1  (114688 + 19328)
#define SMEM_SZ   (114688 + 2 * 19328)

extern __shared__ char c2sm[];

__global__ void __launch_bounds__(256, 1)
conv2_mma_kernel(const float* __restrict__ b2) {
    const int tid  = threadIdx.x;
    const int wid  = tid >> 5;
    const int lane = tid & 31;
    const int wy = wid >> 2;        // 0..1  (M group of 32)
    const int wx = wid & 3;         // 0..3  (N group of 32)
    const int g  = lane >> 2;       // 0..7
    const int c  = lane & 3;        // 0..3
    const int lt  = blockIdx.x;     // 0..7   l-tile of 128
    const int c2h = blockIdx.y;     // 0..1
    const int b   = blockIdx.z;     // 0..31
    const int l0  = lt * 128;

    uint4* sA = reinterpret_cast<uint4*>(c2sm);
    char* spt[2] = {c2sm + SPT_OFF0, c2sm + SPT_OFF1};

    // stage packed A (both planes) for this c2 half
    {
        const uint4* gA = g_Apk + c2h * APK_U4;
#pragma unroll 4
        for (int i = tid; i < APK_U4; i += 256) sA[i] = gA[i];
    }

    // spike tile construct: spT[j][c1] bf16, j = l - l0 + 3
    auto construct = [&](int t, char* buf) {
        const unsigned char* gs = g_s1 + ((size_t)(t * B_ + b) * C1_) * LEN_;
#pragma unroll 1
        for (int i = tid; i < 64 * SPT_ROWS; i += 256) {
            int c1 = i / SPT_ROWS, j = i - c1 * SPT_ROWS;
            int l = l0 - 3 + j;
            unsigned short val = 0;
            if (l >= 0 && l < LEN_ && gs[c1 * LEN_ + l]) val = 0x3F80;
            *reinterpret_cast<unsigned short*>(buf + j * SPT_PITCH + c1 * 2) = val;
        }
    };

    construct(0, spt[0]);
    __syncthreads();

    // thread's 4 c2 rows and their biases
    float bb[2][2];
#pragma unroll
    for (int mt = 0; mt < 2; ++mt)
#pragma unroll
        for (int hf = 0; hf < 2; ++hf)
            bb[mt][hf] = b2[c2h * 64 + wy * 32 + mt * 16 + g + hf * 8];

    float v[2][4][4];
#pragma unroll
    for (int mt = 0; mt < 2; ++mt)
#pragma unroll
        for (int nt = 0; nt < 4; ++nt)
#pragma unroll
            for (int e = 0; e < 4; ++e) v[mt][nt][e] = 0.f;
    float accs[2][2] = {{0.f, 0.f}, {0.f, 0.f}};

#pragma unroll 1
    for (int t = 0; t < TT_; ++t) {
        const char* curB = spt[t & 1];

        float d[2][4][4];
#pragma unroll
        for (int mt = 0; mt < 2; ++mt)
#pragma unroll
            for (int nt = 0; nt < 4; ++nt)
#pragma unroll
                for (int e = 0; e < 4; ++e) d[mt][nt][e] = 0.f;

#pragma unroll 1
        for (int chunk = 0; chunk < 28; ++chunk) {
            const int koff = chunk >> 2, q = chunk & 3;
            uint4 ahi[2], alo[2];
#pragma unroll
            for (int mt = 0; mt < 2; ++mt) {
                int mi = wy * 2 + mt;
                ahi[mt] = sA[((0 + mi) * 28 + chunk) * 32 + lane];
                alo[mt] = sA[((4 + mi) * 28 + chunk) * 32 + lane];
            }
            // B fragments for 4 n-tiles (each: 2 conflict-free LDS.32)
            unsigned b0[4], b1[4];
            const char* brow = curB + (size_t)(wx * 32 + g + koff) * SPT_PITCH
                             + q * 32 + c * 4;
#pragma unroll
            for (int nt = 0; nt < 4; ++nt) {
                b0[nt] = *reinterpret_cast<const unsigned*>(brow + nt * 8 * SPT_PITCH);
                b1[nt] = *reinterpret_cast<const unsigned*>(brow + nt * 8 * SPT_PITCH + 16);
            }
            // hi pass then lo pass (8-deep independent chains per accumulator)
#pragma unroll
            for (int nt = 0; nt < 4; ++nt) {
                MMA16816(d[0][nt], ahi[0], b0[nt], b1[nt]);
                MMA16816(d[1][nt], ahi[1], b0[nt], b1[nt]);
            }
#pragma unroll
            for (int nt = 0; nt < 4; ++nt) {
                MMA16816(d[0][nt], alo[0], b0[nt], b1[nt]);
                MMA16816(d[1][nt], alo[1], b0[nt], b1[nt]);
            }
        }

        // build next t's spike tile (overlaps with mma drain)
        if (t + 1 < TT_) construct(t + 1, spt[(t + 1) & 1]);

        // fused LIF2 on register accumulators
#pragma unroll
        for (int mt = 0; mt < 2; ++mt)
#pragma unroll
            for (int nt = 0; nt < 4; ++nt)
#pragma unroll
                for (int e = 0; e < 4; ++e) {
                    int hf = e >> 1;
                    float h = 2.f * (d[mt][nt][e] + bb[mt][hf]);
                    float vv = v[mt][nt][e];
                    vv = vv + __fdiv_rn(h - vv, 0.9f);
                    if (vv >= 0.5f) { accs[mt][hf] += 1.f; vv = 0.f; }
                    v[mt][nt][e] = vv;
                }

        __syncthreads();
    }

    // exact integer-valued pooling
#pragma unroll
    for (int mt = 0; mt < 2; ++mt)
#pragma unroll
        for (int hf = 0; hf < 2; ++hf) {
            int c2 = c2h * 64 + wy * 32 + mt * 16 + g + hf * 8;
            atomicAdd(&g_pool[b * C2_ + c2], accs[mt][hf]);
        }
}

// ============================================================================
// Kernel 3: zero pool (graph-replay safe)
// ============================================================================
__global__ void zero_pool_kernel() {
    int i = blockIdx.x * 256 + threadIdx.x;
    if (i < B_ * C2_) g_pool[i] = 0.f;
}

// ============================================================================
// Kernel 4: FC  out[b][n] = (pool[b]/ (T*L)) . fcw[n] + fcb[n]
// ============================================================================
__global__ void fc_kernel(const float* __restrict__ fcw,
                          const float* __restrict__ fcb,
                          float* __restrict__ out) {
    const int tid = threadIdx.x;
    if (tid < B_ * 4) {
        int b = tid >> 2, n = tid & 3;
        float s = 0.f;
#pragma unroll 8
        for (int c = 0; c < C2_; ++c)
            s += g_pool[b * C2_ + c] * fcw[n * C2_ + c];
        out[b * 4 + n] = s * (1.f / (float)(TT_ * LEN_)) + fcb[n];
    }
}

// ============================================================================
extern "C" void kernel_launch(void* const* d_in, const int* in_sizes, int n_in,
                              void* d_out, int out_size) {
    const float* x   = (const float*)d_in[0];
    const float* w1  = (const float*)d_in[1];
    const float* b1  = (const float*)d_in[2];
    const float* w2  = (const float*)d_in[3];
    const float* b2  = (const float*)d_in[4];
    const float* fcw = (const float*)d_in[5];
    const float* fcb = (const float*)d_in[6];
    float* out = (float*)d_out;

    cudaFuncSetAttribute(conv2_mma_kernel,
                         cudaFuncAttributeMaxDynamicSharedMemorySize, SMEM_SZ);

    transpose_kernel<<<dim3(TT_ / 32, LEN_ / 32, B_ * CIN_), dim3(32, 8)>>>(x);
    conv1_kernel<<<dim3(LEN_ / 128, B_, TT_), 256>>>(w1, b1);
    w2prep_kernel<<<56, 256>>>(w2);
    zero_pool_kernel<<<16, 256>>>();
    conv2_mma_kernel<<<dim3(8, 2, B_), 256, SMEM_SZ>>>(b2);
    fc_kernel<<<1, 128>>>(fcw, fcb, out);
}

// round 4
// speedup vs baseline: 1.4810x; 1.3340x over previous
#include <cuda_runtime.h>
#include <cuda_bf16.h>
#include <cstdint>

#define B_    32
#define CIN_  12
#define LEN_  1024
#define TT_   64
#define C1_   64
#define C2_   128

// Scratch (device globals; no runtime allocation)
__device__ float         g_xT[TT_ * B_ * CIN_ * LEN_];            // [t][b][cin][l]
__device__ unsigned char g_s1T[(size_t)TT_ * B_ * LEN_ * C1_];    // [t][b][l][c1] spikes
__device__ uint4         g_Apk[7168];   // packed int8 w2 frags: [c2h][plane][mi][chunk][lane]
__device__ float         g_pool[B_ * C2_];

typedef unsigned long long u64;

// ---- packed f32x2 helpers (conv1 FFMA2 path) ----
__device__ __forceinline__ u64 pack2(float lo, float hi) {
    u64 r;
    asm("mov.b64 %0, {%1, %2};" : "=l"(r) : "f"(lo), "f"(hi));
    return r;
}
__device__ __forceinline__ void unpack2(u64 v, float& lo, float& hi) {
    asm("mov.b64 {%0, %1}, %2;" : "=f"(lo), "=f"(hi) : "l"(v));
}
__device__ __forceinline__ void ffma2(u64& d, u64 a, u64 b) {
    asm("fma.rn.f32x2 %0, %1, %2, %0;" : "+l"(d) : "l"(a), "l"(b));
}

// ---- warp MMA: m16n8k32 s8.s8.s32 (baseline PTX, ok at .target sm_103) ----
#define IMMA16832(D, A, B0, B1)                                              \
    asm volatile(                                                            \
        "mma.sync.aligned.m16n8k32.row.col.s32.s8.s8.s32 "                   \
        "{%0,%1,%2,%3}, {%4,%5,%6,%7}, {%8,%9}, {%0,%1,%2,%3};"              \
        : "+r"((D)[0]), "+r"((D)[1]), "+r"((D)[2]), "+r"((D)[3])             \
        : "r"((A).x), "r"((A).y), "r"((A).z), "r"((A).w), "r"(B0), "r"(B1))

// ============================================================================
// Kernel 0: transpose x [b][cin][l][t] -> g_xT [t][b][cin][l]
// ============================================================================
__global__ void __launch_bounds__(256) transpose_kernel(const float* __restrict__ x) {
    __shared__ float tile[32][33];
    const int bc = blockIdx.z;
    const int t0 = blockIdx.x * 32;
    const int l0 = blockIdx.y * 32;
    const int tx = threadIdx.x;
    const int ty = threadIdx.y;
    const float* xb = x + (size_t)bc * LEN_ * TT_;
#pragma unroll
    for (int j = 0; j < 4; ++j)
        tile[ty + j * 8][tx] = xb[(size_t)(l0 + ty + j * 8) * TT_ + t0 + tx];
    __syncthreads();
#pragma unroll
    for (int j = 0; j < 4; ++j)
        g_xT[((size_t)(t0 + ty + j * 8) * (B_ * CIN_) + bc) * LEN_ + l0 + tx] =
            tile[tx][ty + j * 8];
}

// ============================================================================
// Kernel 1: conv1 (12->64, K=7) + LIF1 (tau=1 -> stateless spike), FFMA2.
// Emits spikes TRANSPOSED: g_s1T[t][b][l][c1] via smem tile (coalesced out).
// ============================================================================
__global__ void __launch_bounds__(256) conv1_kernel(const float* __restrict__ w1,
                                                    const float* __restrict__ b1) {
    __shared__ float ws[84 * 68];
    __shared__ float xs[12][136];
    __shared__ unsigned char st[128 * 80];   // [l_local][c1], pitch 80

    const int tid = threadIdx.x;
    const int l0  = blockIdx.x * 128;
    const int b   = blockIdx.y;
    const int t   = blockIdx.z;

    for (int i = tid; i < C1_ * 84; i += 256) {
        int c1 = i / 84, r = i % 84;
        ws[r * 68 + c1] = w1[i];
    }
    const float* xb = g_xT + ((size_t)(t * B_ + b) * CIN_) * LEN_;
    for (int i = tid; i < 12 * 134; i += 256) {
        int cin = i / 134, j = i % 134;
        int l = l0 - 3 + j;
        xs[cin][j] = (l >= 0 && l < LEN_) ? xb[cin * LEN_ + l] : 0.f;
    }
    __syncthreads();

    const int c1g = tid >> 5;
    const int lg  = tid & 31;

    u64 acc[8][2];
#pragma unroll
    for (int c = 0; c < 8; ++c) { acc[c][0] = 0ull; acc[c][1] = 0ull; }

#pragma unroll 1
    for (int cin = 0; cin < 12; ++cin) {
        const float* sp = &xs[cin][lg * 4];
        float4 a0 = *reinterpret_cast<const float4*>(sp);
        float4 a1 = *reinterpret_cast<const float4*>(sp + 4);
        float4 a2 = *reinterpret_cast<const float4*>(sp + 8);
        float sv[12] = {a0.x, a0.y, a0.z, a0.w, a1.x, a1.y, a1.z, a1.w,
                        a2.x, a2.y, a2.z, a2.w};
        u64 pv[9];
#pragma unroll
        for (int j = 0; j < 9; ++j) pv[j] = pack2(sv[j], sv[j + 1]);
#pragma unroll
        for (int k = 0; k < 7; ++k) {
            const float* wp = &ws[(cin * 7 + k) * 68 + c1g * 8];
            float4 w0 = *reinterpret_cast<const float4*>(wp);
            float4 w1v = *reinterpret_cast<const float4*>(wp + 4);
            float wr[8] = {w0.x, w0.y, w0.z, w0.w, w1v.x, w1v.y, w1v.z, w1v.w};
#pragma unroll
            for (int c = 0; c < 8; ++c) {
                u64 wb = pack2(wr[c], wr[c]);
                ffma2(acc[c][0], pv[k], wb);
                ffma2(acc[c][1], pv[k + 2], wb);
            }
        }
    }

    // spikes for 8 c1 x 4 l -> byte matrix, write rows into st
    unsigned char sp8[4][8];
#pragma unroll
    for (int c = 0; c < 8; ++c) {
        float bb = b1[c1g * 8 + c];
        float v0, v1, v2, v3;
        unpack2(acc[c][0], v0, v1);
        unpack2(acc[c][1], v2, v3);
        sp8[0][c] = (2.f * (v0 + bb) >= 0.5f) ? 1 : 0;
        sp8[1][c] = (2.f * (v1 + bb) >= 0.5f) ? 1 : 0;
        sp8[2][c] = (2.f * (v2 + bb) >= 0.5f) ? 1 : 0;
        sp8[3][c] = (2.f * (v3 + bb) >= 0.5f) ? 1 : 0;
    }
#pragma unroll
    for (int i = 0; i < 4; ++i) {
        u64 v = 0;
#pragma unroll
        for (int c = 0; c < 8; ++c) v |= (u64)sp8[i][c] << (8 * c);
        *reinterpret_cast<u64*>(st + (lg * 4 + i) * 80 + c1g * 8) = v;
    }
    __syncthreads();

    // coalesced write-out: 128 rows x 64 B
    unsigned char* dst = g_s1T + ((size_t)(t * B_ + b) * LEN_ + l0) * 64;
#pragma unroll
    for (int j = 0; j < 2; ++j) {
        int idx = tid * 2 + j;
        int row = idx >> 2, q = idx & 3;
        uint4 val = *reinterpret_cast<const uint4*>(st + row * 80 + q * 16);
        *reinterpret_cast<uint4*>(dst + row * 64 + q * 16) = val;
    }
}

// ============================================================================
// Kernel 2a: quantize + pack w2 into IMMA fragment order, 2 s8 planes.
// q = round(w * 2^15); hi = (q+128)>>8; lo = q - hi*256. Exact: q = hi*256+lo.
// chunk = koff*2 + h, covers c1 = 32h..32h+31 at shift koff.
// ============================================================================
__global__ void __launch_bounds__(256) w2prep_kernel(const float* __restrict__ w2) {
    int idx = blockIdx.x * 256 + threadIdx.x;
    if (idx >= 7168) return;
    int lane = idx & 31;
    int r    = idx >> 5;
    int chunk = r % 14;
    int r2    = r / 14;
    int mi    = r2 & 3;
    int plane = (r2 >> 2) & 1;
    int c2h   = r2 >> 3;
    int g = lane >> 2, c = lane & 3;
    int h = chunk & 1, koff = chunk >> 1;
    int m0 = c2h * 64 + mi * 16;
    int c1b = 32 * h + 4 * c;

    auto pk4 = [&](int m, int c1s) -> unsigned {
        unsigned rr = 0;
#pragma unroll
        for (int j = 0; j < 4; ++j) {
            float w = w2[m * 448 + (c1s + j) * 7 + koff];
            int q = __float2int_rn(w * 32768.f);
            int hi = (q + 128) >> 8;
            int lo = q - (hi << 8);
            int val = plane ? lo : hi;
            rr |= ((unsigned)(val & 0xFF)) << (8 * j);
        }
        return rr;
    };
    uint4 out;
    out.x = pk4(m0 + g,     c1b);
    out.y = pk4(m0 + g + 8, c1b);
    out.z = pk4(m0 + g,     c1b + 16);
    out.w = pk4(m0 + g + 8, c1b + 16);
    g_Apk[idx] = out;
}

// ============================================================================
// Kernel 2b: conv2 via IMMA s8 (2 exact planes) + fused LIF2.
// Block: 64 c2 (c2h) x 64 l; 8 warps (wy 2 x wx 4), warp tile M=32, N=16.
// A frags staged once (57344 B); spikes copied per t into double-buffered
// spT[70][80] bytes. LIF state in registers across t. 2 blocks/SM.
// ============================================================================
#define APK_U4   3584
#define SPT_PITCH 80
#define SPT_ROWS  70
#define SPT_BYTES (SPT_ROWS * SPT_PITCH)
#define SPT_OFF0  57344
#define SPT_OFF1  (57344 + SPT_BYTES)
#define SMEM_SZ   (57344 + 2 * SPT_BYTES)

extern __shared__ char c2sm[];

__global__ void __launch_bounds__(256, 2)
conv2_mma_kernel(const float* __restrict__ b2) {
    const int tid  = threadIdx.x;
    const int wid  = tid >> 5;
    const int lane = tid & 31;
    const int wy = wid >> 2;        // 0..1  M group of 32
    const int wx = wid & 3;         // 0..3  N group of 16
    const int g  = lane >> 2;
    const int c  = lane & 3;
    const int lt  = blockIdx.x;     // 0..15
    const int c2h = blockIdx.y;     // 0..1
    const int b   = blockIdx.z;     // 0..31
    const int l0  = lt * 64;

    uint4* sA = reinterpret_cast<uint4*>(c2sm);
    char* spt[2] = {c2sm + SPT_OFF0, c2sm + SPT_OFF1};

    {
        const uint4* gA = g_Apk + c2h * APK_U4;
#pragma unroll 7
        for (int i = tid; i < APK_U4; i += 256) sA[i] = gA[i];
    }

    // per-t spike tile copy: spT[j][c1] bytes, j = l - l0 + 3 (70 rows x 64 B)
    auto construct = [&](int t, char* buf) {
        const uint4* gs = reinterpret_cast<const uint4*>(
            g_s1T + ((size_t)(t * B_ + b) * LEN_) * 64);
#pragma unroll 2
        for (int i = tid; i < SPT_ROWS * 4; i += 256) {
            int j = i >> 2, q = i & 3;
            int l = l0 - 3 + j;
            uint4 val = make_uint4(0, 0, 0, 0);
            if (l >= 0 && l < LEN_) val = gs[l * 4 + q];
            *reinterpret_cast<uint4*>(buf + j * SPT_PITCH + q * 16) = val;
        }
    };

    construct(0, spt[0]);
    __syncthreads();

    float bb[2][2];
#pragma unroll
    for (int mt = 0; mt < 2; ++mt)
#pragma unroll
        for (int hf = 0; hf < 2; ++hf)
            bb[mt][hf] = 2.f * b2[c2h * 64 + wy * 32 + mt * 16 + g + hf * 8];

    float v[2][2][4];
#pragma unroll
    for (int mt = 0; mt < 2; ++mt)
#pragma unroll
        for (int nt = 0; nt < 2; ++nt)
#pragma unroll
            for (int e = 0; e < 4; ++e) v[mt][nt][e] = 0.f;
    float accs[2][2] = {{0.f, 0.f}, {0.f, 0.f}};

    const float SCALE = 6.103515625e-05f;   // 2^-14 (covers GAIN*2^-15)

#pragma unroll 1
    for (int t = 0; t < TT_; ++t) {
        const char* curB = spt[t & 1];

        int dh[2][2][4], dl[2][2][4];
#pragma unroll
        for (int mt = 0; mt < 2; ++mt)
#pragma unroll
            for (int nt = 0; nt < 2; ++nt)
#pragma unroll
                for (int e = 0; e < 4; ++e) { dh[mt][nt][e] = 0; dl[mt][nt][e] = 0; }

#pragma unroll 1
        for (int chunk = 0; chunk < 14; ++chunk) {
            const int koff = chunk >> 1, h = chunk & 1;
            uint4 ah[2], al[2];
#pragma unroll
            for (int mt = 0; mt < 2; ++mt) {
                int mi = wy * 2 + mt;
                ah[mt] = sA[((0 + mi) * 14 + chunk) * 32 + lane];
                al[mt] = sA[((4 + mi) * 14 + chunk) * 32 + lane];
            }
            unsigned b0[2], b1[2];
            const char* brow = curB + (size_t)(wx * 16 + g + koff) * SPT_PITCH
                             + h * 32 + c * 4;
#pragma unroll
            for (int nt = 0; nt < 2; ++nt) {
                b0[nt] = *reinterpret_cast<const unsigned*>(brow + nt * 8 * SPT_PITCH);
                b1[nt] = *reinterpret_cast<const unsigned*>(brow + nt * 8 * SPT_PITCH + 16);
            }
#pragma unroll
            for (int nt = 0; nt < 2; ++nt) {
                IMMA16832(dh[0][nt], ah[0], b0[nt], b1[nt]);
                IMMA16832(dh[1][nt], ah[1], b0[nt], b1[nt]);
            }
#pragma unroll
            for (int nt = 0; nt < 2; ++nt) {
                IMMA16832(dl[0][nt], al[0], b0[nt], b1[nt]);
                IMMA16832(dl[1][nt], al[1], b0[nt], b1[nt]);
            }
        }

        if (t + 1 < TT_) construct(t + 1, spt[(t + 1) & 1]);

        // fused LIF2: h = 2*(q*2^-15 + b2) = q*2^-14 + 2*b2, q exact integer
#pragma unroll
        for (int mt = 0; mt < 2; ++mt)
#pragma unroll
            for (int nt = 0; nt < 2; ++nt)
#pragma unroll
                for (int e = 0; e < 4; ++e) {
                    int hf = e >> 1;
                    int q = dl[mt][nt][e] + (dh[mt][nt][e] << 8);
                    float hval = fmaf((float)q, SCALE, bb[mt][hf]);
                    float vv = v[mt][nt][e];
                    vv = vv + __fdiv_rn(hval - vv, 0.9f);
                    if (vv >= 0.5f) { accs[mt][hf] += 1.f; vv = 0.f; }
                    v[mt][nt][e] = vv;
                }

        __syncthreads();
    }

#pragma unroll
    for (int mt = 0; mt < 2; ++mt)
#pragma unroll
        for (int hf = 0; hf < 2; ++hf) {
            int c2 = c2h * 64 + wy * 32 + mt * 16 + g + hf * 8;
            atomicAdd(&g_pool[b * C2_ + c2], accs[mt][hf]);
        }
}

// ============================================================================
// Kernel 3: zero pool (graph-replay safe)
// ============================================================================
__global__ void zero_pool_kernel() {
    int i = blockIdx.x * 256 + threadIdx.x;
    if (i < B_ * C2_) g_pool[i] = 0.f;
}

// ============================================================================
// Kernel 4: FC
// ============================================================================
__global__ void fc_kernel(const float* __restrict__ fcw,
                          const float* __restrict__ fcb,
                          float* __restrict__ out) {
    const int tid = threadIdx.x;
    if (tid < B_ * 4) {
        int b = tid >> 2, n = tid & 3;
        float s = 0.f;
#pragma unroll 8
        for (int c = 0; c < C2_; ++c)
            s += g_pool[b * C2_ + c] * fcw[n * C2_ + c];
        out[b * 4 + n] = s * (1.f / (float)(TT_ * LEN_)) + fcb[n];
    }
}

// ============================================================================
extern "C" void kernel_launch(void* const* d_in, const int* in_sizes, int n_in,
                              void* d_out, int out_size) {
    const float* x   = (const float*)d_in[0];
    const float* w1  = (const float*)d_in[1];
    const float* b1  = (const float*)d_in[2];
    const float* w2  = (const float*)d_in[3];
    const float* b2  = (const float*)d_in[4];
    const float* fcw = (const float*)d_in[5];
    const float* fcb = (const float*)d_in[6];
    float* out = (float*)d_out;

    cudaFuncSetAttribute(conv2_mma_kernel,
                         cudaFuncAttributeMaxDynamicSharedMemorySize, SMEM_SZ);

    transpose_kernel<<<dim3(TT_ / 32, LEN_ / 32, B_ * CIN_), dim3(32, 8)>>>(x);
    conv1_kernel<<<dim3(LEN_ / 128, B_, TT_), 256>>>(w1, b1);
    w2prep_kernel<<<28, 256>>>(w2);
    zero_pool_kernel<<<16, 256>>>();
    conv2_mma_kernel<<<dim3(16, 2, B_), 256, SMEM_SZ>>>(b2);
    fc_kernel<<<1, 128>>>(fcw, fcb, out);
}

// round 5
// speedup vs baseline: 1.5052x; 1.0164x over previous
#include <cuda_runtime.h>
#include <cuda_bf16.h>
#include <cstdint>

#define B_    32
#define CIN_  12
#define LEN_  1024
#define TT_   64
#define C1_   64
#define C2_   128

// Scratch (device globals; no runtime allocation)
__device__ float         g_xT[TT_ * B_ * CIN_ * LEN_];            // [t][b][cin][l]
__device__ unsigned char g_s1T[(size_t)TT_ * B_ * LEN_ * C1_];    // [t][b][l][c1] spikes
__device__ uint4         g_Apk[7168];   // packed int8 w2 frags: [c2h][plane][mi][chunk][lane]
__device__ float         g_pool[B_ * C2_];

typedef unsigned long long u64;

// ---- packed f32x2 helpers (conv1 FFMA2 path) ----
__device__ __forceinline__ u64 pack2(float lo, float hi) {
    u64 r;
    asm("mov.b64 %0, {%1, %2};" : "=l"(r) : "f"(lo), "f"(hi));
    return r;
}
__device__ __forceinline__ void unpack2(u64 v, float& lo, float& hi) {
    asm("mov.b64 {%0, %1}, %2;" : "=f"(lo), "=f"(hi) : "l"(v));
}
__device__ __forceinline__ void ffma2(u64& d, u64 a, u64 b) {
    asm("fma.rn.f32x2 %0, %1, %2, %0;" : "+l"(d) : "l"(a), "l"(b));
}

// ---- warp MMA: m16n8k32 s8.s8.s32 (baseline PTX, ok at .target sm_103) ----
#define IMMA16832(D, A, B0, B1)                                              \
    asm volatile(                                                            \
        "mma.sync.aligned.m16n8k32.row.col.s32.s8.s8.s32 "                   \
        "{%0,%1,%2,%3}, {%4,%5,%6,%7}, {%8,%9}, {%0,%1,%2,%3};"              \
        : "+r"((D)[0]), "+r"((D)[1]), "+r"((D)[2]), "+r"((D)[3])             \
        : "r"((A).x), "r"((A).y), "r"((A).z), "r"((A).w), "r"(B0), "r"(B1))

// ============================================================================
// Kernel 0: transpose x [b][cin][l][t] -> g_xT [t][b][cin][l]
// ============================================================================
__global__ void __launch_bounds__(256) transpose_kernel(const float* __restrict__ x) {
    __shared__ float tile[32][33];
    const int bc = blockIdx.z;
    const int t0 = blockIdx.x * 32;
    const int l0 = blockIdx.y * 32;
    const int tx = threadIdx.x;
    const int ty = threadIdx.y;
    const float* xb = x + (size_t)bc * LEN_ * TT_;
#pragma unroll
    for (int j = 0; j < 4; ++j)
        tile[ty + j * 8][tx] = xb[(size_t)(l0 + ty + j * 8) * TT_ + t0 + tx];
    __syncthreads();
#pragma unroll
    for (int j = 0; j < 4; ++j)
        g_xT[((size_t)(t0 + ty + j * 8) * (B_ * CIN_) + bc) * LEN_ + l0 + tx] =
            tile[tx][ty + j * 8];
}

// ============================================================================
// Kernel 1: conv1 (12->64, K=7) + LIF1 (tau=1 -> stateless spike), FFMA2.
// Emits spikes TRANSPOSED: g_s1T[t][b][l][c1] via smem tile (coalesced out).
// ============================================================================
__global__ void __launch_bounds__(256) conv1_kernel(const float* __restrict__ w1,
                                                    const float* __restrict__ b1) {
    __shared__ float ws[84 * 68];
    __shared__ float xs[12][136];
    __shared__ unsigned char st[128 * 80];   // [l_local][c1], pitch 80

    const int tid = threadIdx.x;
    const int l0  = blockIdx.x * 128;
    const int b   = blockIdx.y;
    const int t   = blockIdx.z;

    for (int i = tid; i < C1_ * 84; i += 256) {
        int c1 = i / 84, r = i % 84;
        ws[r * 68 + c1] = w1[i];
    }
    const float* xb = g_xT + ((size_t)(t * B_ + b) * CIN_) * LEN_;
    for (int i = tid; i < 12 * 134; i += 256) {
        int cin = i / 134, j = i % 134;
        int l = l0 - 3 + j;
        xs[cin][j] = (l >= 0 && l < LEN_) ? xb[cin * LEN_ + l] : 0.f;
    }
    __syncthreads();

    const int c1g = tid >> 5;
    const int lg  = tid & 31;

    u64 acc[8][2];
#pragma unroll
    for (int c = 0; c < 8; ++c) { acc[c][0] = 0ull; acc[c][1] = 0ull; }

#pragma unroll 1
    for (int cin = 0; cin < 12; ++cin) {
        const float* sp = &xs[cin][lg * 4];
        float4 a0 = *reinterpret_cast<const float4*>(sp);
        float4 a1 = *reinterpret_cast<const float4*>(sp + 4);
        float4 a2 = *reinterpret_cast<const float4*>(sp + 8);
        float sv[12] = {a0.x, a0.y, a0.z, a0.w, a1.x, a1.y, a1.z, a1.w,
                        a2.x, a2.y, a2.z, a2.w};
        u64 pv[9];
#pragma unroll
        for (int j = 0; j < 9; ++j) pv[j] = pack2(sv[j], sv[j + 1]);
#pragma unroll
        for (int k = 0; k < 7; ++k) {
            const float* wp = &ws[(cin * 7 + k) * 68 + c1g * 8];
            float4 w0 = *reinterpret_cast<const float4*>(wp);
            float4 w1v = *reinterpret_cast<const float4*>(wp + 4);
            float wr[8] = {w0.x, w0.y, w0.z, w0.w, w1v.x, w1v.y, w1v.z, w1v.w};
#pragma unroll
            for (int c = 0; c < 8; ++c) {
                u64 wb = pack2(wr[c], wr[c]);
                ffma2(acc[c][0], pv[k], wb);
                ffma2(acc[c][1], pv[k + 2], wb);
            }
        }
    }

    // spikes for 8 c1 x 4 l -> byte matrix, write rows into st
    unsigned char sp8[4][8];
#pragma unroll
    for (int c = 0; c < 8; ++c) {
        float bb = b1[c1g * 8 + c];
        float v0, v1, v2, v3;
        unpack2(acc[c][0], v0, v1);
        unpack2(acc[c][1], v2, v3);
        sp8[0][c] = (2.f * (v0 + bb) >= 0.5f) ? 1 : 0;
        sp8[1][c] = (2.f * (v1 + bb) >= 0.5f) ? 1 : 0;
        sp8[2][c] = (2.f * (v2 + bb) >= 0.5f) ? 1 : 0;
        sp8[3][c] = (2.f * (v3 + bb) >= 0.5f) ? 1 : 0;
    }
#pragma unroll
    for (int i = 0; i < 4; ++i) {
        u64 v = 0;
#pragma unroll
        for (int c = 0; c < 8; ++c) v |= (u64)sp8[i][c] << (8 * c);
        *reinterpret_cast<u64*>(st + (lg * 4 + i) * 80 + c1g * 8) = v;
    }
    __syncthreads();

    // coalesced write-out: 128 rows x 64 B
    unsigned char* dst = g_s1T + ((size_t)(t * B_ + b) * LEN_ + l0) * 64;
#pragma unroll
    for (int j = 0; j < 2; ++j) {
        int idx = tid * 2 + j;
        int row = idx >> 2, q = idx & 3;
        uint4 val = *reinterpret_cast<const uint4*>(st + row * 80 + q * 16);
        *reinterpret_cast<uint4*>(dst + row * 64 + q * 16) = val;
    }
}

// ============================================================================
// Kernel 2a: quantize + pack w2 into IMMA fragment order (2 exact s8 planes),
// and zero g_pool (merged so conv2 is the 4th launch -> ncu captures it).
// q = round(w * 2^15); hi = (q+128)>>8; lo = q - hi*256. Exact: q = hi*256+lo.
// ============================================================================
__global__ void __launch_bounds__(256) w2prep_kernel(const float* __restrict__ w2) {
    int idx = blockIdx.x * 256 + threadIdx.x;
    if (idx < B_ * C2_) g_pool[idx] = 0.f;
    if (idx >= 7168) return;
    int lane = idx & 31;
    int r    = idx >> 5;
    int chunk = r % 14;
    int r2    = r / 14;
    int mi    = r2 & 3;
    int plane = (r2 >> 2) & 1;
    int c2h   = r2 >> 3;
    int g = lane >> 2, c = lane & 3;
    int h = chunk & 1, koff = chunk >> 1;
    int m0 = c2h * 64 + mi * 16;
    int c1b = 32 * h + 4 * c;

    auto pk4 = [&](int m, int c1s) -> unsigned {
        unsigned rr = 0;
#pragma unroll
        for (int j = 0; j < 4; ++j) {
            float w = w2[m * 448 + (c1s + j) * 7 + koff];
            int q = __float2int_rn(w * 32768.f);
            int hi = (q + 128) >> 8;
            int lo = q - (hi << 8);
            int val = plane ? lo : hi;
            rr |= ((unsigned)(val & 0xFF)) << (8 * j);
        }
        return rr;
    };
    uint4 out;
    out.x = pk4(m0 + g,     c1b);
    out.y = pk4(m0 + g + 8, c1b);
    out.z = pk4(m0 + g,     c1b + 16);
    out.w = pk4(m0 + g + 8, c1b + 16);
    g_Apk[idx] = out;
}

// ============================================================================
// Kernel 2b: conv2 via IMMA s8 (2 exact planes) + fused LIF2.
// construct(t+1) hoisted BEFORE the MMA loop so LDG latency hides under IMMAs.
// ============================================================================
#define APK_U4   3584
#define SPT_PITCH 80
#define SPT_ROWS  70
#define SPT_BYTES (SPT_ROWS * SPT_PITCH)
#define SPT_OFF0  57344
#define SPT_OFF1  (57344 + SPT_BYTES)
#define SMEM_SZ   (57344 + 2 * SPT_BYTES)

extern __shared__ char c2sm[];

__global__ void __launch_bounds__(256, 2)
conv2_mma_kernel(const float* __restrict__ b2) {
    const int tid  = threadIdx.x;
    const int wid  = tid >> 5;
    const int lane = tid & 31;
    const int wy = wid >> 2;        // 0..1  M group of 32
    const int wx = wid & 3;         // 0..3  N group of 16
    const int g  = lane >> 2;
    const int c  = lane & 3;
    const int lt  = blockIdx.x;     // 0..15
    const int c2h = blockIdx.y;     // 0..1
    const int b   = blockIdx.z;     // 0..31
    const int l0  = lt * 64;

    uint4* sA = reinterpret_cast<uint4*>(c2sm);
    char* spt[2] = {c2sm + SPT_OFF0, c2sm + SPT_OFF1};

    {
        const uint4* gA = g_Apk + c2h * APK_U4;
#pragma unroll 7
        for (int i = tid; i < APK_U4; i += 256) sA[i] = gA[i];
    }

    // per-t spike tile copy: spT[j][c1] bytes, j = l - l0 + 3 (70 rows x 64 B)
    auto construct = [&](int t, char* buf) {
        const uint4* gs = reinterpret_cast<const uint4*>(
            g_s1T + ((size_t)(t * B_ + b) * LEN_) * 64);
#pragma unroll 2
        for (int i = tid; i < SPT_ROWS * 4; i += 256) {
            int j = i >> 2, q = i & 3;
            int l = l0 - 3 + j;
            uint4 val = make_uint4(0, 0, 0, 0);
            if (l >= 0 && l < LEN_) val = gs[l * 4 + q];
            *reinterpret_cast<uint4*>(buf + j * SPT_PITCH + q * 16) = val;
        }
    };

    construct(0, spt[0]);
    __syncthreads();

    float bb[2][2];
#pragma unroll
    for (int mt = 0; mt < 2; ++mt)
#pragma unroll
        for (int hf = 0; hf < 2; ++hf)
            bb[mt][hf] = 2.f * b2[c2h * 64 + wy * 32 + mt * 16 + g + hf * 8];

    float v[2][2][4];
#pragma unroll
    for (int mt = 0; mt < 2; ++mt)
#pragma unroll
        for (int nt = 0; nt < 2; ++nt)
#pragma unroll
            for (int e = 0; e < 4; ++e) v[mt][nt][e] = 0.f;
    float accs[2][2] = {{0.f, 0.f}, {0.f, 0.f}};

    const float SCALE = 6.103515625e-05f;   // 2^-14 (covers GAIN*2^-15)
    const float INV_TAU = 1.0f / 0.9f;

#pragma unroll 1
    for (int t = 0; t < TT_; ++t) {
        const char* curB = spt[t & 1];

        // issue next tile's loads FIRST: LDG latency hides under the MMA phase
        if (t + 1 < TT_) construct(t + 1, spt[(t + 1) & 1]);

        int dh[2][2][4], dl[2][2][4];
#pragma unroll
        for (int mt = 0; mt < 2; ++mt)
#pragma unroll
            for (int nt = 0; nt < 2; ++nt)
#pragma unroll
                for (int e = 0; e < 4; ++e) { dh[mt][nt][e] = 0; dl[mt][nt][e] = 0; }

#pragma unroll 2
        for (int chunk = 0; chunk < 14; ++chunk) {
            const int koff = chunk >> 1, h = chunk & 1;
            uint4 ah[2], al[2];
#pragma unroll
            for (int mt = 0; mt < 2; ++mt) {
                int mi = wy * 2 + mt;
                ah[mt] = sA[((0 + mi) * 14 + chunk) * 32 + lane];
                al[mt] = sA[((4 + mi) * 14 + chunk) * 32 + lane];
            }
            unsigned b0[2], b1[2];
            const char* brow = curB + (size_t)(wx * 16 + g + koff) * SPT_PITCH
                             + h * 32 + c * 4;
#pragma unroll
            for (int nt = 0; nt < 2; ++nt) {
                b0[nt] = *reinterpret_cast<const unsigned*>(brow + nt * 8 * SPT_PITCH);
                b1[nt] = *reinterpret_cast<const unsigned*>(brow + nt * 8 * SPT_PITCH + 16);
            }
#pragma unroll
            for (int nt = 0; nt < 2; ++nt) {
                IMMA16832(dh[0][nt], ah[0], b0[nt], b1[nt]);
                IMMA16832(dh[1][nt], ah[1], b0[nt], b1[nt]);
            }
#pragma unroll
            for (int nt = 0; nt < 2; ++nt) {
                IMMA16832(dl[0][nt], al[0], b0[nt], b1[nt]);
                IMMA16832(dl[1][nt], al[1], b0[nt], b1[nt]);
            }
        }

        // fused LIF2: h = q*2^-14 + 2*b2 (q exact integer); single-rounding fma
#pragma unroll
        for (int mt = 0; mt < 2; ++mt)
#pragma unroll
            for (int nt = 0; nt < 2; ++nt)
#pragma unroll
                for (int e = 0; e < 4; ++e) {
                    int hf = e >> 1;
                    int q = dl[mt][nt][e] + (dh[mt][nt][e] << 8);
                    float hval = fmaf((float)q, SCALE, bb[mt][hf]);
                    float vv = v[mt][nt][e];
                    vv = fmaf(hval - vv, INV_TAU, vv);
                    if (vv >= 0.5f) { accs[mt][hf] += 1.f; vv = 0.f; }
                    v[mt][nt][e] = vv;
                }

        __syncthreads();
    }

#pragma unroll
    for (int mt = 0; mt < 2; ++mt)
#pragma unroll
        for (int hf = 0; hf < 2; ++hf) {
            int c2 = c2h * 64 + wy * 32 + mt * 16 + g + hf * 8;
            atomicAdd(&g_pool[b * C2_ + c2], accs[mt][hf]);
        }
}

// ============================================================================
// Kernel 4: FC
// ============================================================================
__global__ void fc_kernel(const float* __restrict__ fcw,
                          const float* __restrict__ fcb,
                          float* __restrict__ out) {
    const int tid = threadIdx.x;
    if (tid < B_ * 4) {
        int b = tid >> 2, n = tid & 3;
        float s = 0.f;
#pragma unroll 8
        for (int c = 0; c < C2_; ++c)
            s += g_pool[b * C2_ + c] * fcw[n * C2_ + c];
        out[b * 4 + n] = s * (1.f / (float)(TT_ * LEN_)) + fcb[n];
    }
}

// ============================================================================
extern "C" void kernel_launch(void* const* d_in, const int* in_sizes, int n_in,
                              void* d_out, int out_size) {
    const float* x   = (const float*)d_in[0];
    const float* w1  = (const float*)d_in[1];
    const float* b1  = (const float*)d_in[2];
    const float* w2  = (const float*)d_in[3];
    const float* b2  = (const float*)d_in[4];
    const float* fcw = (const float*)d_in[5];
    const float* fcb = (const float*)d_in[6];
    float* out = (float*)d_out;

    cudaFuncSetAttribute(conv2_mma_kernel,
                         cudaFuncAttributeMaxDynamicSharedMemorySize, SMEM_SZ);

    // conv2_mma_kernel is launch #4 -> ncu (-s 5 -c 1 pattern) captures it
    transpose_kernel<<<dim3(TT_ / 32, LEN_ / 32, B_ * CIN_), dim3(32, 8)>>>(x);
    conv1_kernel<<<dim3(LEN_ / 128, B_, TT_), 256>>>(w1, b1);
    w2prep_kernel<<<28, 256>>>(w2);
    conv2_mma_kernel<<<dim3(16, 2, B_), 256, SMEM_SZ>>>(b2);
    fc_kernel<<<1, 128>>>(fcw, fcb, out);
}

// round 6
// speedup vs baseline: 1.5460x; 1.0271x over previous
#include <cuda_runtime.h>
#include <cuda_bf16.h>
#include <cstdint>

#define B_    32
#define CIN_  12
#define LEN_  1024
#define TT_   64
#define C1_   64
#define C2_   128

// Scratch (device globals; no runtime allocation)
__device__ float g_xT[TT_ * B_ * CIN_ * LEN_];   // [t][b][cin][l]
__device__ uint4 g_Apk[7168];   // packed int8 w2 frags: [c2h][plane][mi][chunk][lane]
__device__ float g_pool[B_ * C2_];

typedef unsigned long long u64;

// ---- packed f32x2 helpers ----
__device__ __forceinline__ u64 pack2(float lo, float hi) {
    u64 r;
    asm("mov.b64 %0, {%1, %2};" : "=l"(r) : "f"(lo), "f"(hi));
    return r;
}
__device__ __forceinline__ void unpack2(u64 v, float& lo, float& hi) {
    asm("mov.b64 {%0, %1}, %2;" : "=f"(lo), "=f"(hi) : "l"(v));
}
__device__ __forceinline__ void ffma2(u64& d, u64 a, u64 b) {
    asm("fma.rn.f32x2 %0, %1, %2, %0;" : "+l"(d) : "l"(a), "l"(b));
}

// ---- warp MMA: m16n8k32 s8.s8.s32 ----
#define IMMA16832(D, A, B0, B1)                                              \
    asm volatile(                                                            \
        "mma.sync.aligned.m16n8k32.row.col.s32.s8.s8.s32 "                   \
        "{%0,%1,%2,%3}, {%4,%5,%6,%7}, {%8,%9}, {%0,%1,%2,%3};"              \
        : "+r"((D)[0]), "+r"((D)[1]), "+r"((D)[2]), "+r"((D)[3])             \
        : "r"((A).x), "r"((A).y), "r"((A).z), "r"((A).w), "r"(B0), "r"(B1))

// ============================================================================
// Kernel A: quantize + pack w2 into IMMA fragment order (2 exact s8 planes).
// q = round(w * 2^15); hi = (q+128)>>8; lo = q - hi*256. Exact: q = hi*256+lo.
// ============================================================================
__global__ void __launch_bounds__(256) w2prep_kernel(const float* __restrict__ w2) {
    int idx = blockIdx.x * 256 + threadIdx.x;
    if (idx >= 7168) return;
    int lane = idx & 31;
    int r    = idx >> 5;
    int chunk = r % 14;
    int r2    = r / 14;
    int mi    = r2 & 3;
    int plane = (r2 >> 2) & 1;
    int c2h   = r2 >> 3;
    int g = lane >> 2, c = lane & 3;
    int h = chunk & 1, koff = chunk >> 1;
    int m0 = c2h * 64 + mi * 16;
    int c1b = 32 * h + 4 * c;

    auto pk4 = [&](int m, int c1s) -> unsigned {
        unsigned rr = 0;
#pragma unroll
        for (int j = 0; j < 4; ++j) {
            float w = w2[m * 448 + (c1s + j) * 7 + koff];
            int q = __float2int_rn(w * 32768.f);
            int hi = (q + 128) >> 8;
            int lo = q - (hi << 8);
            int val = plane ? lo : hi;
            rr |= ((unsigned)(val & 0xFF)) << (8 * j);
        }
        return rr;
    };
    uint4 out;
    out.x = pk4(m0 + g,     c1b);
    out.y = pk4(m0 + g + 8, c1b);
    out.z = pk4(m0 + g,     c1b + 16);
    out.w = pk4(m0 + g + 8, c1b + 16);
    g_Apk[idx] = out;
}

// ============================================================================
// Kernel B: transpose x [b][cin][l][t] -> g_xT [t][b][cin][l]
// ============================================================================
__global__ void __launch_bounds__(256) transpose_kernel(const float* __restrict__ x) {
    __shared__ float tile[32][33];
    const int bc = blockIdx.z;
    const int t0 = blockIdx.x * 32;
    const int l0 = blockIdx.y * 32;
    const int tx = threadIdx.x;
    const int ty = threadIdx.y;
    const float* xb = x + (size_t)bc * LEN_ * TT_;
#pragma unroll
    for (int j = 0; j < 4; ++j)
        tile[ty + j * 8][tx] = xb[(size_t)(l0 + ty + j * 8) * TT_ + t0 + tx];
    __syncthreads();
#pragma unroll
    for (int j = 0; j < 4; ++j)
        g_xT[((size_t)(t0 + ty + j * 8) * (B_ * CIN_) + bc) * LEN_ + l0 + tx] =
            tile[tx][ty + j * 8];
}

// ============================================================================
// Kernel C: zero pool (graph-replay safe; also pads launch order so the
// fused kernel is launch #4 for ncu)
// ============================================================================
__global__ void zero_pool_kernel() {
    int i = blockIdx.x * 256 + threadIdx.x;
    if (i < B_ * C2_) g_pool[i] = 0.f;
}

// ============================================================================
// Kernel D (FUSED): conv1(FFMA2)+LIF1 -> spikes in smem -> conv2(IMMA s8,
// 2 exact planes) + LIF2, all inside one t-loop. conv1 runs on the FMA pipe
// (~23% capacity) hidden under the saturated tensor pipe.
//
// Block: 64 c2 (c2h) x 64 l; 8 warps (wy 2 x wx 4), warp tile M=32, N=16.
// Per t: MMA issues over spT[t&1] -> conv1 for t+1 writes spT[(t+1)&1]
//        -> LIF2 on drained accumulators. Double-buffered x slices (xs).
// ============================================================================
// smem byte layout
#define OFF_SA   0
#define OFF_SPT0 57344
#define OFF_SPT1 (57344 + 5760)
#define OFF_XS0  (57344 + 11520)
#define OFF_XS1  (OFF_XS0 + 3840)
#define OFF_WS1  (OFF_XS0 + 7680)
#define SMEM_SZ  (OFF_WS1 + 21504)      // 98048 B
#define SPT_PITCH 80
#define APK_U4   3584

extern __shared__ char fsm[];

__global__ void __launch_bounds__(256, 2)
fused_kernel(const float* __restrict__ b1, const float* __restrict__ b2) {
    const int tid  = threadIdx.x;
    const int wid  = tid >> 5;
    const int lane = tid & 31;
    const int wy = wid >> 2;        // 0..1  M group of 32
    const int wx = wid & 3;         // 0..3  N group of 16
    const int g  = lane >> 2;
    const int c  = lane & 3;
    const int lt  = blockIdx.x;     // 0..15
    const int c2h = blockIdx.y;     // 0..1
    const int b   = blockIdx.z;     // 0..31
    const int l0  = lt * 64;

    uint4*  sA  = reinterpret_cast<uint4*>(fsm + OFF_SA);
    char*   spt[2] = {fsm + OFF_SPT0, fsm + OFF_SPT1};
    float*  xs[2]  = {reinterpret_cast<float*>(fsm + OFF_XS0),
                      reinterpret_cast<float*>(fsm + OFF_XS1)};
    float2* ws1 = reinterpret_cast<float2*>(fsm + OFF_WS1);

    // ---- one-time staging: A fragments + conv1 weight pairs ----
    {
        const uint4* gA = g_Apk + c2h * APK_U4;
#pragma unroll 7
        for (int i = tid; i < APK_U4; i += 256) sA[i] = gA[i];
        // ws1[(cin*7+k)*32 + i] = (w1[2i][cin][k], w1[2i+1][cin][k])
        extern __device__ float g_xT[];  // (decl reuse)
    }
    // w1 is passed via constant path below (see launch wrapper storing to smem)
    // -- actually stage from global w1 pointer provided through b1-4? No:
    // w1 staged via kernel arg (added param)
    // (handled below)

    // conv1 x-slice LDG helper (float4 granularity; guards are exact at 4-float
    // boundaries since l0 % 4 == 0)
    auto ldg_xs = [&](int t) -> float4 {
        float4 v = make_float4(0.f, 0.f, 0.f, 0.f);
        if (tid < 240 && t < TT_) {
            int cin = tid / 20, q = tid % 20;
            int l = l0 - 8 + q * 4;
            if (l >= 0 && l + 3 < LEN_) {
                const float4* src = reinterpret_cast<const float4*>(
                    g_xT + ((size_t)((t * B_ + b) * CIN_) + cin) * LEN_ + l);
                v = *src;
            }
        }
        return v;
    };
    auto sts_xs = [&](float4 v, float* buf) {
        if (tid < 240) {
            int cin = tid / 20, q = tid % 20;
            *reinterpret_cast<float4*>(buf + cin * 80 + q * 4) = v;
        }
    };

    // stage xs(0) now; ws1 staged by threads (see below); then sync
    float4 st0 = ldg_xs(0);
    sts_xs(st0, xs[0]);

    __syncthreads();
    // dummy barrier split: ws1 staging needs w1 pointer — provided via
    // global const pointer array trick is not available; staged in wrapper
    // kernel instead (see w1prep). ws1 lives in GLOBAL g_w1pk and is staged:
    {
        extern __device__ float2 g_w1pk[84 * 32];
#pragma unroll 2
        for (int i = tid; i < 84 * 32; i += 256) ws1[i] = g_w1pk[i];
    }

    const float b1lo = b1[2 * lane];
    const float b1hi = b1[2 * lane + 1];

    // conv1 for timestep t1: xs buf -> spike tile spT (72 rows x 64 c1)
    auto conv1_step = [&](const float* xsb, char* sptb) {
        const int jb = wid * 9;
        u64 acc[9];
#pragma unroll
        for (int r = 0; r < 9; ++r) acc[r] = 0ull;
#pragma unroll 1
        for (int cin = 0; cin < 12; ++cin) {
            const float* xr = xsb + cin * 80 + jb + 2;
            float xv[15];
#pragma unroll
            for (int m = 0; m < 15; ++m) xv[m] = xr[m];
#pragma unroll
            for (int k = 0; k < 7; ++k) {
                float2 wp = ws1[(cin * 7 + k) * 32 + lane];
                u64 wpk = pack2(wp.x, wp.y);
#pragma unroll
                for (int r = 0; r < 9; ++r)
                    ffma2(acc[r], pack2(xv[r + k], xv[r + k]), wpk);
            }
        }
#pragma unroll
        for (int r = 0; r < 9; ++r) {
            int j = jb + r;
            int l = l0 - 3 + j;
            float v0, v1;
            unpack2(acc[r], v0, v1);
            bool in = ((unsigned)l < (unsigned)LEN_);
            unsigned s0 = (in && 2.f * (v0 + b1lo) >= 0.5f) ? 1u : 0u;
            unsigned s1 = (in && 2.f * (v1 + b1hi) >= 0.5f) ? 1u : 0u;
            *reinterpret_cast<unsigned short*>(sptb + j * SPT_PITCH + 2 * lane) =
                (unsigned short)(s0 | (s1 << 8));
        }
    };

    __syncthreads();            // xs(0) + ws1 visible
    conv1_step(xs[0], spt[0]);  // spikes for t=0
    float4 st1 = ldg_xs(1);
    sts_xs(st1, xs[1]);
    __syncthreads();            // spT(0) + xs(1) visible

    float bb[2][2];
#pragma unroll
    for (int mt = 0; mt < 2; ++mt)
#pragma unroll
        for (int hf = 0; hf < 2; ++hf)
            bb[mt][hf] = 2.f * b2[c2h * 64 + wy * 32 + mt * 16 + g + hf * 8];

    float v[2][2][4];
#pragma unroll
    for (int mt = 0; mt < 2; ++mt)
#pragma unroll
        for (int nt = 0; nt < 2; ++nt)
#pragma unroll
            for (int e = 0; e < 4; ++e) v[mt][nt][e] = 0.f;
    float accs[2][2] = {{0.f, 0.f}, {0.f, 0.f}};

    const float SCALE = 6.103515625e-05f;   // 2^-14
    const float INV_TAU = 1.0f / 0.9f;

#pragma unroll 1
    for (int t = 0; t < TT_; ++t) {
        const char* curB = spt[t & 1];

        // issue x loads for t+2 early (latency hides under MMA phase)
        float4 stg = ldg_xs(t + 2);

        int dh[2][2][4], dl[2][2][4];
#pragma unroll
        for (int mt = 0; mt < 2; ++mt)
#pragma unroll
            for (int nt = 0; nt < 2; ++nt)
#pragma unroll
                for (int e = 0; e < 4; ++e) { dh[mt][nt][e] = 0; dl[mt][nt][e] = 0; }

#pragma unroll 2
        for (int chunk = 0; chunk < 14; ++chunk) {
            const int koff = chunk >> 1, h = chunk & 1;
            uint4 ah[2], al[2];
#pragma unroll
            for (int mt = 0; mt < 2; ++mt) {
                int mi = wy * 2 + mt;
                ah[mt] = sA[((0 + mi) * 14 + chunk) * 32 + lane];
                al[mt] = sA[((4 + mi) * 14 + chunk) * 32 + lane];
            }
            unsigned b0[2], b1f[2];
            const char* brow = curB + (size_t)(wx * 16 + g + koff) * SPT_PITCH
                             + h * 32 + c * 4;
#pragma unroll
            for (int nt = 0; nt < 2; ++nt) {
                b0[nt]  = *reinterpret_cast<const unsigned*>(brow + nt * 8 * SPT_PITCH);
                b1f[nt] = *reinterpret_cast<const unsigned*>(brow + nt * 8 * SPT_PITCH + 16);
            }
#pragma unroll
            for (int nt = 0; nt < 2; ++nt) {
                IMMA16832(dh[0][nt], ah[0], b0[nt], b1f[nt]);
                IMMA16832(dh[1][nt], ah[1], b0[nt], b1f[nt]);
            }
#pragma unroll
            for (int nt = 0; nt < 2; ++nt) {
                IMMA16832(dl[0][nt], al[0], b0[nt], b1f[nt]);
                IMMA16832(dl[1][nt], al[1], b0[nt], b1f[nt]);
            }
        }

        // conv1 for t+1 on the FMA pipe (independent of MMA accumulators ->
        // overlaps tensor-pipe drain)
        if (t + 1 < TT_) conv1_step(xs[(t + 1) & 1], spt[(t + 1) & 1]);

        // stage xs(t+2)
        sts_xs(stg, xs[t & 1]);

        // fused LIF2 (waits on tensor drain)
#pragma unroll
        for (int mt = 0; mt < 2; ++mt)
#pragma unroll
            for (int nt = 0; nt < 2; ++nt)
#pragma unroll
                for (int e = 0; e < 4; ++e) {
                    int hf = e >> 1;
                    int q = dl[mt][nt][e] + (dh[mt][nt][e] << 8);
                    float hval = fmaf((float)q, SCALE, bb[mt][hf]);
                    float vv = v[mt][nt][e];
                    vv = fmaf(hval - vv, INV_TAU, vv);
                    if (vv >= 0.5f) { accs[mt][hf] += 1.f; vv = 0.f; }
                    v[mt][nt][e] = vv;
                }

        __syncthreads();
    }

#pragma unroll
    for (int mt = 0; mt < 2; ++mt)
#pragma unroll
        for (int hf = 0; hf < 2; ++hf) {
            int c2 = c2h * 64 + wy * 32 + mt * 16 + g + hf * 8;
            atomicAdd(&g_pool[b * C2_ + c2], accs[mt][hf]);
        }
}

// packed conv1 weight pairs in global (staged to smem by fused kernel)
__device__ float2 g_w1pk[84 * 32];

// ============================================================================
// Kernel E: pack w1 into f32x2 pair order: g_w1pk[(cin*7+k)*32+i] =
// (w1[2i][cin][k], w1[2i+1][cin][k])
// ============================================================================
__global__ void __launch_bounds__(256) w1prep_kernel(const float* __restrict__ w1) {
    int idx = blockIdx.x * 256 + threadIdx.x;
    if (idx >= 84 * 32) return;
    int r = idx >> 5, i = idx & 31;
    float2 p;
    p.x = w1[(2 * i) * 84 + r];
    p.y = w1[(2 * i + 1) * 84 + r];
    g_w1pk[idx] = p;
}

// ============================================================================
// Kernel F: FC
// ============================================================================
__global__ void fc_kernel(const float* __restrict__ fcw,
                          const float* __restrict__ fcb,
                          float* __restrict__ out) {
    const int tid = threadIdx.x;
    if (tid < B_ * 4) {
        int b = tid >> 2, n = tid & 3;
        float s = 0.f;
#pragma unroll 8
        for (int c = 0; c < C2_; ++c)
            s += g_pool[b * C2_ + c] * fcw[n * C2_ + c];
        out[b * 4 + n] = s * (1.f / (float)(TT_ * LEN_)) + fcb[n];
    }
}

// ============================================================================
extern "C" void kernel_launch(void* const* d_in, const int* in_sizes, int n_in,
                              void* d_out, int out_size) {
    const float* x   = (const float*)d_in[0];
    const float* w1  = (const float*)d_in[1];
    const float* b1  = (const float*)d_in[2];
    const float* w2  = (const float*)d_in[3];
    const float* b2  = (const float*)d_in[4];
    const float* fcw = (const float*)d_in[5];
    const float* fcb = (const float*)d_in[6];
    float* out = (float*)d_out;

    cudaFuncSetAttribute(fused_kernel,
                         cudaFuncAttributeMaxDynamicSharedMemorySize, SMEM_SZ);

    w2prep_kernel<<<28, 256>>>(w2);                                   // 1
    transpose_kernel<<<dim3(TT_ / 32, LEN_ / 32, B_ * CIN_), dim3(32, 8)>>>(x); // 2
    w1prep_kernel<<<11, 256>>>(w1);                                   // 3a
    zero_pool_kernel<<<16, 256>>>();                                  // 3b... (4th slot below)
    fused_kernel<<<dim3(16, 2, B_), 256, SMEM_SZ>>>(b1, b2);          // 5th
    fc_kernel<<<1, 128>>>(fcw, fcb, out);
}

// round 7
// speedup vs baseline: 1.6495x; 1.0669x over previous
#include <cuda_runtime.h>
#include <cuda_bf16.h>
#include <cstdint>

#define B_    32
#define CIN_  12
#define LEN_  1024
#define TT_   64
#define C1_   64
#define C2_   128

// Scratch (device globals; no runtime allocation)
__device__ float    g_xT[TT_ * B_ * CIN_ * LEN_];   // [t][b][cin][l]
__device__ uint4    g_Apk[7168];     // packed s8 w2 frags [c2h][plane][mi][chunk][lane]
__device__ unsigned g_Alo[2 * 3584]; // lo plane (h=1) words [c2h][koff][c1w][m]
__device__ float2   g_w1pk[84 * 32]; // conv1 weight pairs
__device__ float    g_pool[B_ * C2_];

typedef unsigned long long u64;

// ---- packed f32x2 helpers ----
__device__ __forceinline__ u64 pack2(float lo, float hi) {
    u64 r;
    asm("mov.b64 %0, {%1, %2};" : "=l"(r) : "f"(lo), "f"(hi));
    return r;
}
__device__ __forceinline__ void unpack2(u64 v, float& lo, float& hi) {
    asm("mov.b64 {%0, %1}, %2;" : "=f"(lo), "=f"(hi) : "l"(v));
}
__device__ __forceinline__ void ffma2(u64& d, u64 a, u64 b) {
    asm("fma.rn.f32x2 %0, %1, %2, %0;" : "+l"(d) : "l"(a), "l"(b));
}
__device__ __forceinline__ void dp4a(int& acc, unsigned a, unsigned b) {
    asm("dp4a.s32.s32 %0, %1, %2, %0;" : "+r"(acc) : "r"(a), "r"(b));
}

// ---- warp MMA: m16n8k32 s8.s8.s32 ----
#define IMMA16832(D, A, B0, B1)                                              \
    asm volatile(                                                            \
        "mma.sync.aligned.m16n8k32.row.col.s32.s8.s8.s32 "                   \
        "{%0,%1,%2,%3}, {%4,%5,%6,%7}, {%8,%9}, {%0,%1,%2,%3};"              \
        : "+r"((D)[0]), "+r"((D)[1]), "+r"((D)[2]), "+r"((D)[3])             \
        : "r"((A).x), "r"((A).y), "r"((A).z), "r"((A).w), "r"(B0), "r"(B1))

// ============================================================================
// Kernel A: quantize + pack w2. Exact 2-plane split at scale 2^15:
// q = round(w*2^15); hi = (q+128)>>8; lo = q - hi*256 (both s8, q = hi*256+lo).
// Outputs: g_Apk (IMMA frags, all chunks) and g_Alo (h=1 lo words for dp4a).
// ============================================================================
__global__ void __launch_bounds__(256) w2prep_kernel(const float* __restrict__ w2) {
    int idx = blockIdx.x * 256 + threadIdx.x;
    if (idx >= 7168) return;

    // ---- IMMA fragment packing ----
    {
        int lane = idx & 31;
        int r    = idx >> 5;
        int chunk = r % 14;
        int r2    = r / 14;
        int mi    = r2 & 3;
        int plane = (r2 >> 2) & 1;
        int c2h   = r2 >> 3;
        int g = lane >> 2, c = lane & 3;
        int h = chunk & 1, koff = chunk >> 1;
        int m0 = c2h * 64 + mi * 16;
        int c1b = 32 * h + 4 * c;

        auto pk4 = [&](int m, int c1s) -> unsigned {
            unsigned rr = 0;
#pragma unroll
            for (int j = 0; j < 4; ++j) {
                float w = w2[m * 448 + (c1s + j) * 7 + koff];
                int q = __float2int_rn(w * 32768.f);
                int hi = (q + 128) >> 8;
                int lo = q - (hi << 8);
                int val = plane ? lo : hi;
                rr |= ((unsigned)(val & 0xFF)) << (8 * j);
            }
            return rr;
        };
        uint4 out;
        out.x = pk4(m0 + g,     c1b);
        out.y = pk4(m0 + g + 8, c1b);
        out.z = pk4(m0 + g,     c1b + 16);
        out.w = pk4(m0 + g + 8, c1b + 16);
        g_Apk[idx] = out;
    }

    // ---- dp4a lo words (h=1 half: c1 in [32,64)) ----
    {
        int c2h  = idx / 3584;
        int rem  = idx % 3584;
        int koff = rem >> 9;            // 0..6
        int c1w  = (rem >> 6) & 7;      // 0..7
        int mloc = rem & 63;
        int m = c2h * 64 + mloc;
        unsigned rr = 0;
#pragma unroll
        for (int j = 0; j < 4; ++j) {
            int c1 = 32 + 4 * c1w + j;
            float w = w2[m * 448 + c1 * 7 + koff];
            int q = __float2int_rn(w * 32768.f);
            int hi = (q + 128) >> 8;
            int lo = q - (hi << 8);
            rr |= ((unsigned)(lo & 0xFF)) << (8 * j);
        }
        g_Alo[idx] = rr;
    }
}

// ============================================================================
// Kernel B: transpose x [b][cin][l][t] -> g_xT [t][b][cin][l]
// ============================================================================
__global__ void __launch_bounds__(256) transpose_kernel(const float* __restrict__ x) {
    __shared__ float tile[32][33];
    const int bc = blockIdx.z;
    const int t0 = blockIdx.x * 32;
    const int l0 = blockIdx.y * 32;
    const int tx = threadIdx.x;
    const int ty = threadIdx.y;
    const float* xb = x + (size_t)bc * LEN_ * TT_;
#pragma unroll
    for (int j = 0; j < 4; ++j)
        tile[ty + j * 8][tx] = xb[(size_t)(l0 + ty + j * 8) * TT_ + t0 + tx];
    __syncthreads();
#pragma unroll
    for (int j = 0; j < 4; ++j)
        g_xT[((size_t)(t0 + ty + j * 8) * (B_ * CIN_) + bc) * LEN_ + l0 + tx] =
            tile[tx][ty + j * 8];
}

// ============================================================================
// Kernel C: pack w1 pairs + zero g_pool (merged so fused kernel is launch #4)
// ============================================================================
__global__ void __launch_bounds__(256) w1prep_kernel(const float* __restrict__ w1) {
    int idx = blockIdx.x * 256 + threadIdx.x;
    if (idx < B_ * C2_) g_pool[idx] = 0.f;
    if (idx < 84 * 32) {
        int r = idx >> 5, i = idx & 31;
        float2 p;
        p.x = w1[(2 * i) * 84 + r];
        p.y = w1[(2 * i + 1) * 84 + r];
        g_w1pk[idx] = p;
    }
}

// ============================================================================
// Kernel D (FUSED): conv1(FFMA2)+LIF1 -> spikes in smem ->
// conv2 = IMMA(hi full + lo h=0) on tensor pipe  +  dp4a(lo h=1) on alu pipe
// + fused LIF2. Per-t phases all hide under the saturated tensor pipe.
// ============================================================================
#define SPT_PITCH 80
#define OFF_SA   0                       //  57344 B  IMMA A frags
#define OFF_ALO  57344                   //  14336 B  dp4a lo words
#define OFF_SPT0 (OFF_ALO + 14336)       //   5760 B
#define OFF_SPT1 (OFF_SPT0 + 5760)       //   5760 B
#define OFF_XS0  (OFF_SPT1 + 5760)       //   3840 B
#define OFF_XS1  (OFF_XS0 + 3840)        //   3840 B
#define OFF_WS1  (OFF_XS1 + 3840)        //  21504 B
#define SMEM_SZ  (OFF_WS1 + 21504)       // 112384 B
#define APK_U4   3584

extern __shared__ char fsm[];

__global__ void __launch_bounds__(256, 2)
fused_kernel(const float* __restrict__ b1, const float* __restrict__ b2) {
    const int tid  = threadIdx.x;
    const int wid  = tid >> 5;
    const int lane = tid & 31;
    const int wy = wid >> 2;        // 0..1  M group of 32
    const int wx = wid & 3;         // 0..3  N group of 16
    const int g  = lane >> 2;
    const int c  = lane & 3;
    const int lt  = blockIdx.x;     // 0..15
    const int c2h = blockIdx.y;     // 0..1
    const int b   = blockIdx.z;     // 0..31
    const int l0  = lt * 64;

    uint4*    sA   = reinterpret_cast<uint4*>(fsm + OFF_SA);
    unsigned* sAlo = reinterpret_cast<unsigned*>(fsm + OFF_ALO);
    char*     spt[2] = {fsm + OFF_SPT0, fsm + OFF_SPT1};
    float*    xs[2]  = {reinterpret_cast<float*>(fsm + OFF_XS0),
                        reinterpret_cast<float*>(fsm + OFF_XS1)};
    float2*   ws1 = reinterpret_cast<float2*>(fsm + OFF_WS1);

    // ---- one-time staging ----
    {
        const uint4* gA = g_Apk + c2h * APK_U4;
#pragma unroll 7
        for (int i = tid; i < APK_U4; i += 256) sA[i] = gA[i];
        const unsigned* gL = g_Alo + c2h * 3584;
#pragma unroll 7
        for (int i = tid; i < 3584; i += 256) sAlo[i] = gL[i];
#pragma unroll 2
        for (int i = tid; i < 84 * 32; i += 256) ws1[i] = g_w1pk[i];
    }

    auto ldg_xs = [&](int t) -> float4 {
        float4 v = make_float4(0.f, 0.f, 0.f, 0.f);
        if (tid < 240 && t < TT_) {
            int cin = tid / 20, q = tid % 20;
            int l = l0 - 8 + q * 4;
            if (l >= 0 && l + 3 < LEN_) {
                v = *reinterpret_cast<const float4*>(
                    g_xT + ((size_t)((t * B_ + b) * CIN_) + cin) * LEN_ + l);
            }
        }
        return v;
    };
    auto sts_xs = [&](float4 v, float* buf) {
        if (tid < 240) {
            int cin = tid / 20, q = tid % 20;
            *reinterpret_cast<float4*>(buf + cin * 80 + q * 4) = v;
        }
    };

    float4 st0 = ldg_xs(0);
    sts_xs(st0, xs[0]);

    const float b1lo = b1[2 * lane];
    const float b1hi = b1[2 * lane + 1];

    // conv1 for one timestep: xs buf -> spike tile (pack2 hoisted per cin)
    auto conv1_step = [&](const float* xsb, char* sptb) {
        const int jb = wid * 9;
        u64 acc[9];
#pragma unroll
        for (int r = 0; r < 9; ++r) acc[r] = 0ull;
#pragma unroll 1
        for (int cin = 0; cin < 12; ++cin) {
            const float* xr = xsb + cin * 80 + jb + 2;
            u64 pv[15];
#pragma unroll
            for (int m = 0; m < 15; ++m) {
                float xv = xr[m];
                pv[m] = pack2(xv, xv);
            }
#pragma unroll
            for (int k = 0; k < 7; ++k) {
                float2 wp = ws1[(cin * 7 + k) * 32 + lane];
                u64 wpk = pack2(wp.x, wp.y);
#pragma unroll
                for (int r = 0; r < 9; ++r)
                    ffma2(acc[r], pv[r + k], wpk);
            }
        }
#pragma unroll
        for (int r = 0; r < 9; ++r) {
            int j = jb + r;
            int l = l0 - 3 + j;
            float v0, v1;
            unpack2(acc[r], v0, v1);
            bool in = ((unsigned)l < (unsigned)LEN_);
            unsigned s0 = (in && 2.f * (v0 + b1lo) >= 0.5f) ? 1u : 0u;
            unsigned s1 = (in && 2.f * (v1 + b1hi) >= 0.5f) ? 1u : 0u;
            *reinterpret_cast<unsigned short*>(sptb + j * SPT_PITCH + 2 * lane) =
                (unsigned short)(s0 | (s1 << 8));
        }
    };

    __syncthreads();            // staging + xs(0) visible
    conv1_step(xs[0], spt[0]);  // spikes for t=0
    float4 st1 = ldg_xs(1);
    sts_xs(st1, xs[1]);
    __syncthreads();            // spT(0) + xs(1) visible

    float bb[2][2];
#pragma unroll
    for (int mt = 0; mt < 2; ++mt)
#pragma unroll
        for (int hf = 0; hf < 2; ++hf)
            bb[mt][hf] = 2.f * b2[c2h * 64 + wy * 32 + mt * 16 + g + hf * 8];

    float v[2][2][4];
#pragma unroll
    for (int mt = 0; mt < 2; ++mt)
#pragma unroll
        for (int nt = 0; nt < 2; ++nt)
#pragma unroll
            for (int e = 0; e < 4; ++e) v[mt][nt][e] = 0.f;
    float accs[2][2] = {{0.f, 0.f}, {0.f, 0.f}};

    const float SCALE = 6.103515625e-05f;   // 2^-14
    const float INV_TAU = 1.0f / 0.9f;

#pragma unroll 1
    for (int t = 0; t < TT_; ++t) {
        const char* curB = spt[t & 1];

        float4 stg = ldg_xs(t + 2);   // early: hides under MMA phase

        int dh[2][2][4], dl[2][2][4], ds[2][2][4];
#pragma unroll
        for (int mt = 0; mt < 2; ++mt)
#pragma unroll
            for (int nt = 0; nt < 2; ++nt)
#pragma unroll
                for (int e = 0; e < 4; ++e) {
                    dh[mt][nt][e] = 0; dl[mt][nt][e] = 0; ds[mt][nt][e] = 0;
                }

        // ---- tensor phase: hi (h0+h1) + lo (h0 only) = 12 IMMAs per koff ----
#pragma unroll 1
        for (int koff = 0; koff < 7; ++koff) {
            const int ch0 = koff * 2, ch1 = ch0 + 1;
            uint4 ah0[2], ah1[2], al0[2];
#pragma unroll
            for (int mt = 0; mt < 2; ++mt) {
                int mi = wy * 2 + mt;
                ah0[mt] = sA[((0 + mi) * 14 + ch0) * 32 + lane];
                ah1[mt] = sA[((0 + mi) * 14 + ch1) * 32 + lane];
                al0[mt] = sA[((4 + mi) * 14 + ch0) * 32 + lane];
            }
            const char* brow = curB + (size_t)(wx * 16 + g + koff) * SPT_PITCH + c * 4;
            unsigned b00[2], b01[2], b10[2], b11[2];
#pragma unroll
            for (int nt = 0; nt < 2; ++nt) {
                const char* p = brow + nt * 8 * SPT_PITCH;
                b00[nt] = *reinterpret_cast<const unsigned*>(p);
                b01[nt] = *reinterpret_cast<const unsigned*>(p + 16);
                b10[nt] = *reinterpret_cast<const unsigned*>(p + 32);
                b11[nt] = *reinterpret_cast<const unsigned*>(p + 48);
            }
#pragma unroll
            for (int nt = 0; nt < 2; ++nt) {
                IMMA16832(dh[0][nt], ah0[0], b00[nt], b01[nt]);
                IMMA16832(dh[1][nt], ah0[1], b00[nt], b01[nt]);
                IMMA16832(dh[0][nt], ah1[0], b10[nt], b11[nt]);
                IMMA16832(dh[1][nt], ah1[1], b10[nt], b11[nt]);
                IMMA16832(dl[0][nt], al0[0], b00[nt], b01[nt]);
                IMMA16832(dl[1][nt], al0[1], b00[nt], b01[nt]);
            }
        }

        // ---- alu phase: lo (h=1) via dp4a, independent accumulators ----
#pragma unroll 1
        for (int koff = 0; koff < 7; ++koff) {
            const char* bbase = curB + (size_t)(wx * 16 + 2 * c + koff) * SPT_PITCH + 32;
            const unsigned* abase = sAlo + koff * 512 + wy * 32 + g;
#pragma unroll
            for (int c1w = 0; c1w < 8; ++c1w) {
                unsigned bw00 = *reinterpret_cast<const unsigned*>(bbase + c1w * 4);
                unsigned bw01 = *reinterpret_cast<const unsigned*>(bbase + c1w * 4 + SPT_PITCH);
                unsigned bw10 = *reinterpret_cast<const unsigned*>(bbase + c1w * 4 + 8 * SPT_PITCH);
                unsigned bw11 = *reinterpret_cast<const unsigned*>(bbase + c1w * 4 + 9 * SPT_PITCH);
                const unsigned* ap = abase + c1w * 64;
                unsigned a00 = ap[0], a01 = ap[8], a10 = ap[16], a11 = ap[24];
                dp4a(ds[0][0][0], a00, bw00); dp4a(ds[0][0][1], a00, bw01);
                dp4a(ds[0][0][2], a01, bw00); dp4a(ds[0][0][3], a01, bw01);
                dp4a(ds[0][1][0], a00, bw10); dp4a(ds[0][1][1], a00, bw11);
                dp4a(ds[0][1][2], a01, bw10); dp4a(ds[0][1][3], a01, bw11);
                dp4a(ds[1][0][0], a10, bw00); dp4a(ds[1][0][1], a10, bw01);
                dp4a(ds[1][0][2], a11, bw00); dp4a(ds[1][0][3], a11, bw01);
                dp4a(ds[1][1][0], a10, bw10); dp4a(ds[1][1][1], a10, bw11);
                dp4a(ds[1][1][2], a11, bw10); dp4a(ds[1][1][3], a11, bw11);
            }
        }

        // ---- fma phase: conv1 for t+1 ----
        if (t + 1 < TT_) conv1_step(xs[(t + 1) & 1], spt[(t + 1) & 1]);

        sts_xs(stg, xs[t & 1]);

        // ---- LIF2: q = (hi<<8) + lo(IMMA h0) + lo(dp4a h1), exact integer ----
#pragma unroll
        for (int mt = 0; mt < 2; ++mt)
#pragma unroll
            for (int nt = 0; nt < 2; ++nt)
#pragma unroll
                for (int e = 0; e < 4; ++e) {
                    int hf = e >> 1;
                    int q = dl[mt][nt][e] + ds[mt][nt][e] + (dh[mt][nt][e] << 8);
                    float hval = fmaf((float)q, SCALE, bb[mt][hf]);
                    float vv = v[mt][nt][e];
                    vv = fmaf(hval - vv, INV_TAU, vv);
                    if (vv >= 0.5f) { accs[mt][hf] += 1.f; vv = 0.f; }
                    v[mt][nt][e] = vv;
                }

        __syncthreads();
    }

#pragma unroll
    for (int mt = 0; mt < 2; ++mt)
#pragma unroll
        for (int hf = 0; hf < 2; ++hf) {
            int c2 = c2h * 64 + wy * 32 + mt * 16 + g + hf * 8;
            atomicAdd(&g_pool[b * C2_ + c2], accs[mt][hf]);
        }
}

// ============================================================================
// Kernel E: FC
// ============================================================================
__global__ void fc_kernel(const float* __restrict__ fcw,
                          const float* __restrict__ fcb,
                          float* __restrict__ out) {
    const int tid = threadIdx.x;
    if (tid < B_ * 4) {
        int b = tid >> 2, n = tid & 3;
        float s = 0.f;
#pragma unroll 8
        for (int c = 0; c < C2_; ++c)
            s += g_pool[b * C2_ + c] * fcw[n * C2_ + c];
        out[b * 4 + n] = s * (1.f / (float)(TT_ * LEN_)) + fcb[n];
    }
}

// ============================================================================
extern "C" void kernel_launch(void* const* d_in, const int* in_sizes, int n_in,
                              void* d_out, int out_size) {
    const float* x   = (const float*)d_in[0];
    const float* w1  = (const float*)d_in[1];
    const float* b1  = (const float*)d_in[2];
    const float* w2  = (const float*)d_in[3];
    const float* b2  = (const float*)d_in[4];
    const float* fcw = (const float*)d_in[5];
    const float* fcb = (const float*)d_in[6];
    float* out = (float*)d_out;

    cudaFuncSetAttribute(fused_kernel,
                         cudaFuncAttributeMaxDynamicSharedMemorySize, SMEM_SZ);

    w2prep_kernel<<<28, 256>>>(w2);                                             // 1
    transpose_kernel<<<dim3(TT_ / 32, LEN_ / 32, B_ * CIN_), dim3(32, 8)>>>(x); // 2
    w1prep_kernel<<<16, 256>>>(w1);                                             // 3
    fused_kernel<<<dim3(16, 2, B_), 256, SMEM_SZ>>>(b1, b2);                    // 4 <- ncu
    fc_kernel<<<1, 128>>>(fcw, fcb, out);                                       // 5
}